// round 1
// baseline (speedup 1.0000x reference)
#include <cuda_runtime.h>

#define NN 50000
#define DD 512
#define EPS 1e-5f

// -------- scratch (static __device__ allocations; no cudaMalloc allowed) ----
__device__ float g_agg[(size_t)NN * DD];   // 102.4 MB aggregation buffer
__device__ int   g_cnt[NN];
__device__ float g_colsum[DD];
__device__ float g_colsumsq[DD];
__device__ float g_mu[DD];
__device__ float g_rstd[DD];

// -------- 1. zero scratch ---------------------------------------------------
__global__ void zero_kernel() {
    const size_t stride = (size_t)gridDim.x * blockDim.x;
    const size_t i = (size_t)blockIdx.x * blockDim.x + threadIdx.x;
    const size_t total4 = (size_t)NN * DD / 4;
    float4 z = make_float4(0.f, 0.f, 0.f, 0.f);
    for (size_t idx = i; idx < total4; idx += stride)
        ((float4*)g_agg)[idx] = z;
    if (i < NN) g_cnt[i] = 0;
    if (i < DD) { g_colsum[i] = 0.f; g_colsumsq[i] = 0.f; }
}

// -------- 2. edge scatter-add: agg[dst] += x[src], cnt[dst] += 1 ------------
__global__ __launch_bounds__(256) void agg_kernel(
    const float* __restrict__ x, const int* __restrict__ ei, int E)
{
    long long t = (long long)blockIdx.x * blockDim.x + threadIdx.x;
    int e = (int)(t >> 7);          // 128 threads per edge
    if (e >= E) return;
    int c = ((int)t & 127) * 4;     // float4 chunk
    int src = __ldg(&ei[e]);
    int dst = __ldg(&ei[E + e]);
    float4 v = *(const float4*)&x[(size_t)src * DD + c];
    float* a = &g_agg[(size_t)dst * DD + c];
    atomicAdd(a + 0, v.x);
    atomicAdd(a + 1, v.y);
    atomicAdd(a + 2, v.z);
    atomicAdd(a + 3, v.w);
    if (c == 0) atomicAdd(&g_cnt[dst], 1);
}

// -------- 3. scale rows by 1/max(cnt,1) -------------------------------------
__global__ void mean_kernel(int N) {
    int i = blockIdx.x;
    if (i >= N) return;
    float inv = 1.0f / (float)max(g_cnt[i], 1);
    float4* row = (float4*)&g_agg[(size_t)i * DD];
    float4 v = row[threadIdx.x];
    v.x *= inv; v.y *= inv; v.z *= inv; v.w *= inv;
    row[threadIdx.x] = v;
}

// -------- 4. fused GEMM: h = mean_agg @ Wl^T + x @ Wr^T + bl ----------------
// 128x128 tile, BK=16, 256 threads, 8x8 per thread. K runs 0..1023:
// first 512 uses (g_agg, Wl), second 512 uses (x, Wr).
__global__ __launch_bounds__(256) void gemm_kernel(
    const float* __restrict__ x, const float* __restrict__ Wl,
    const float* __restrict__ Wr, const float* __restrict__ bl,
    float* __restrict__ hout, int N)
{
    __shared__ __align__(16) float As[16][128];
    __shared__ __align__(16) float Bs[16][128];

    const int tid  = threadIdx.x;
    const int row0 = blockIdx.y * 128;
    const int col0 = blockIdx.x * 128;

    const int trow = (tid / 16) * 8;
    const int tcol = (tid % 16) * 8;

    float acc[8][8];
#pragma unroll
    for (int i = 0; i < 8; ++i)
#pragma unroll
        for (int j = 0; j < 8; ++j) acc[i][j] = 0.f;

    const int a_r = tid >> 2;          // 0..63
    const int a_c = (tid & 3) * 4;     // 0,4,8,12
    const int b_j = tid >> 1;          // 0..127
    const int b_k = (tid & 1) * 8;     // 0 or 8

    for (int kt = 0; kt < 64; ++kt) {
        const int k0 = (kt & 31) * 16;
        const float* A = (kt < 32) ? g_agg : x;
        const float* W = (kt < 32) ? Wl : Wr;

#pragma unroll
        for (int it = 0; it < 2; ++it) {
            int r = a_r + it * 64;
            int grow = row0 + r;
            float4 v = make_float4(0.f, 0.f, 0.f, 0.f);
            if (grow < N) v = *(const float4*)&A[(size_t)grow * DD + k0 + a_c];
            As[a_c + 0][r] = v.x; As[a_c + 1][r] = v.y;
            As[a_c + 2][r] = v.z; As[a_c + 3][r] = v.w;
        }
#pragma unroll
        for (int it = 0; it < 2; ++it) {
            int kk = b_k + it * 4;
            float4 w = *(const float4*)&W[(size_t)(col0 + b_j) * DD + k0 + kk];
            Bs[kk + 0][b_j] = w.x; Bs[kk + 1][b_j] = w.y;
            Bs[kk + 2][b_j] = w.z; Bs[kk + 3][b_j] = w.w;
        }
        __syncthreads();

#pragma unroll
        for (int k = 0; k < 16; ++k) {
            float4 a0 = *(const float4*)&As[k][trow];
            float4 a1 = *(const float4*)&As[k][trow + 4];
            float4 b0 = *(const float4*)&Bs[k][tcol];
            float4 b1 = *(const float4*)&Bs[k][tcol + 4];
            float ra[8] = {a0.x, a0.y, a0.z, a0.w, a1.x, a1.y, a1.z, a1.w};
            float rb[8] = {b0.x, b0.y, b0.z, b0.w, b1.x, b1.y, b1.z, b1.w};
#pragma unroll
            for (int i = 0; i < 8; ++i)
#pragma unroll
                for (int j = 0; j < 8; ++j)
                    acc[i][j] = fmaf(ra[i], rb[j], acc[i][j]);
        }
        __syncthreads();
    }

    float4 bv0 = *(const float4*)&bl[col0 + tcol];
    float4 bv1 = *(const float4*)&bl[col0 + tcol + 4];
#pragma unroll
    for (int i = 0; i < 8; ++i) {
        int grow = row0 + trow + i;
        if (grow >= N) break;
        float4 o0, o1;
        o0.x = acc[i][0] + bv0.x; o0.y = acc[i][1] + bv0.y;
        o0.z = acc[i][2] + bv0.z; o0.w = acc[i][3] + bv0.w;
        o1.x = acc[i][4] + bv1.x; o1.y = acc[i][5] + bv1.y;
        o1.z = acc[i][6] + bv1.z; o1.w = acc[i][7] + bv1.w;
        float4* dst = (float4*)&hout[(size_t)grow * DD + col0 + tcol];
        dst[0] = o0;
        dst[1] = o1;
    }
}

// -------- 5. per-column sum / sumsq over nodes ------------------------------
__global__ void colstats_kernel(const float* __restrict__ h, int N) {
    int c = blockIdx.x * blockDim.x + threadIdx.x;   // 0..511
    int chunk = (N + gridDim.y - 1) / gridDim.y;
    int r0 = blockIdx.y * chunk;
    int r1 = min(r0 + chunk, N);
    float s = 0.f, sq = 0.f;
    for (int i = r0; i < r1; ++i) {
        float v = h[(size_t)i * DD + c];
        s += v;
        sq = fmaf(v, v, sq);
    }
    atomicAdd(&g_colsum[c], s);
    atomicAdd(&g_colsumsq[c], sq);
}

// -------- 6. finalize mean / rstd -------------------------------------------
__global__ void stats_kernel(int N) {
    int c = threadIdx.x;
    float invn = 1.0f / (float)N;
    float mu = g_colsum[c] * invn;
    float var = g_colsumsq[c] * invn - mu * mu;
    g_mu[c] = mu;
    g_rstd[c] = rsqrtf(var + EPS);
}

// -------- 7. out = relu((h-mu)*rstd*gamma + beta) + x  (in-place on h) ------
__global__ __launch_bounds__(256) void final_kernel(
    const float* __restrict__ x, const float* __restrict__ gamma,
    const float* __restrict__ beta, float* __restrict__ out, int N)
{
    size_t idx = (size_t)blockIdx.x * blockDim.x + threadIdx.x;
    size_t total4 = (size_t)N * DD / 4;
    if (idx >= total4) return;
    int c = (int)((idx * 4) & (DD - 1));
    float4 h  = ((float4*)out)[idx];
    float4 xv = ((const float4*)x)[idx];
    float4 mu = *(const float4*)&g_mu[c];
    float4 rs = *(const float4*)&g_rstd[c];
    float4 ga = *(const float4*)&gamma[c];
    float4 be = *(const float4*)&beta[c];
    float4 o;
    o.x = fmaxf(fmaf((h.x - mu.x) * rs.x, ga.x, be.x), 0.f) + xv.x;
    o.y = fmaxf(fmaf((h.y - mu.y) * rs.y, ga.y, be.y), 0.f) + xv.y;
    o.z = fmaxf(fmaf((h.z - mu.z) * rs.z, ga.z, be.z), 0.f) + xv.z;
    o.w = fmaxf(fmaf((h.w - mu.w) * rs.w, ga.w, be.w), 0.f) + xv.w;
    ((float4*)out)[idx] = o;
}

// ---------------------------------------------------------------------------
extern "C" void kernel_launch(void* const* d_in, const int* in_sizes, int n_in,
                              void* d_out, int out_size)
{
    const float* x  = (const float*)d_in[0];
    const int*   ei = (const int*)d_in[1];
    const float* Wl = (const float*)d_in[2];
    const float* bl = (const float*)d_in[3];
    const float* Wr = (const float*)d_in[4];
    const float* ga = (const float*)d_in[5];
    const float* be = (const float*)d_in[6];
    float* out = (float*)d_out;

    int N = in_sizes[0] / DD;
    int E = in_sizes[1] / 2;

    zero_kernel<<<256, 256>>>();

    long long work = (long long)E * 128;
    agg_kernel<<<(int)((work + 255) / 256), 256>>>(x, ei, E);

    mean_kernel<<<N, 128>>>(N);

    dim3 ggrid(DD / 128, (N + 127) / 128);
    gemm_kernel<<<ggrid, 256>>>(x, Wl, Wr, bl, out, N);

    dim3 cgrid(DD / 128, 128);
    colstats_kernel<<<cgrid, 128>>>(out, N);

    stats_kernel<<<1, DD>>>(N);

    size_t tot4 = (size_t)N * DD / 4;
    final_kernel<<<(int)((tot4 + 255) / 256), 256>>>(x, ga, be, out, N);
}

// round 3
// speedup vs baseline: 1.6973x; 1.6973x over previous
#include <cuda_runtime.h>
#include <cuda_bf16.h>
#include <cstdint>

#define NN 50000
#define DD 512
#define EPS 1e-5f

// -------- scratch (static __device__; no cudaMalloc allowed) ----------------
__device__ float g_agg[(size_t)NN * DD];   // raw sums (mean folded into GEMM)
__device__ int   g_cnt[NN];
__device__ float g_colsum[DD];
__device__ float g_colsumsq[DD];
__device__ float g_mu[DD];
__device__ float g_rstd[DD];

// -------- helpers ------------------------------------------------------------
__device__ __forceinline__ uint32_t smem_u32(const void* p) {
    uint32_t a;
    asm("{ .reg .u64 t; cvta.to.shared.u64 t, %1; cvt.u32.u64 %0, t; }"
        : "=r"(a) : "l"(p));
    return a;
}

#define LDSM4(r0, r1, r2, r3, addr) \
    asm volatile("ldmatrix.sync.aligned.m8n8.x4.shared.b16 {%0,%1,%2,%3}, [%4];" \
        : "=r"(r0), "=r"(r1), "=r"(r2), "=r"(r3) : "r"(addr))

#define MMA_BF16(d, a, b0, b1) \
    asm volatile("mma.sync.aligned.m16n8k16.row.col.f32.bf16.bf16.f32 " \
        "{%0,%1,%2,%3}, {%4,%5,%6,%7}, {%8,%9}, {%0,%1,%2,%3};" \
        : "+f"((d)[0]), "+f"((d)[1]), "+f"((d)[2]), "+f"((d)[3]) \
        : "r"((a)[0]), "r"((a)[1]), "r"((a)[2]), "r"((a)[3]), "r"(b0), "r"(b1))

// tile config
#define BM 128
#define BN 128
#define BK 32
#define ROWSTR 40                 // bf16 elems per smem row (80 B, pad for LDSM)
#define TILE_E (128 * ROWSTR)     // 5120 bf16 per tile array
#define SMEM_BYTES (2 * 4 * TILE_E * 2)   // 2 stages x {Ahi,Alo,Bhi,Blo} = 81920

// -------- bf16-split tensor GEMM: h = mean_agg@Wl^T + x@Wr^T + bl -----------
__global__ __launch_bounds__(256, 1) void gemm_mma(
    const float* __restrict__ x, const float* __restrict__ Wl,
    const float* __restrict__ Wr, const float* __restrict__ bl,
    float* __restrict__ out, int N)
{
    extern __shared__ __nv_bfloat16 sm[];
    const uint32_t s0 = smem_u32(sm);
    const int tid = threadIdx.x;
    const int lane = tid & 31, wid = tid >> 5;
    const int row0 = blockIdx.y * BM;
    const int col0 = blockIdx.x * BN;
    const int warp_m = (wid >> 1) * 32;
    const int warp_n = (wid & 1) * 64;

    // inverse counts for this thread's 4 A-rows (mean fold)
    float inv[4];
#pragma unroll
    for (int it = 0; it < 4; ++it) {
        int rg = row0 + it * 32 + (tid >> 3);
        int c = (rg < N) ? g_cnt[rg] : 1;
        inv[it] = 1.0f / (float)max(c, 1);
    }

    float acc[2][8][4];
#pragma unroll
    for (int mf = 0; mf < 2; ++mf)
#pragma unroll
        for (int nf = 0; nf < 8; ++nf)
#pragma unroll
            for (int i = 0; i < 4; ++i) acc[mf][nf][i] = 0.f;

    float4 sa[4], sb[4];   // LDG staging registers

    auto ldg_tile = [&](int kt) {
        const int k0 = (kt & 15) * BK;
        const float* A = (kt < 16) ? g_agg : x;
        const float* W = (kt < 16) ? Wl : Wr;
#pragma unroll
        for (int it = 0; it < 4; ++it) {
            int idx = it * 256 + tid;
            int r = idx >> 3, c4 = idx & 7;
            int rg = row0 + r;
            sa[it] = (rg < N) ? *(const float4*)&A[(size_t)rg * DD + k0 + c4 * 4]
                              : make_float4(0.f, 0.f, 0.f, 0.f);
            sb[it] = *(const float4*)&W[(size_t)(col0 + r) * DD + k0 + c4 * 4];
        }
    };

    auto cvt_sts = [&](int s, bool isagg) {
        __nv_bfloat16* ahi = sm + (s * 4 + 0) * TILE_E;
        __nv_bfloat16* alo = sm + (s * 4 + 1) * TILE_E;
        __nv_bfloat16* bhi = sm + (s * 4 + 2) * TILE_E;
        __nv_bfloat16* blo = sm + (s * 4 + 3) * TILE_E;
#pragma unroll
        for (int it = 0; it < 4; ++it) {
            int idx = it * 256 + tid;
            int r = idx >> 3, c4 = idx & 7;
            int e = r * ROWSTR + c4 * 4;
            float4 v = sa[it];
            if (isagg) { float iv = inv[it]; v.x *= iv; v.y *= iv; v.z *= iv; v.w *= iv; }
            float vv[4] = {v.x, v.y, v.z, v.w};
            float4 w = sb[it];
            float wv[4] = {w.x, w.y, w.z, w.w};
#pragma unroll
            for (int j = 0; j < 4; j += 2) {
                __nv_bfloat16 h0 = __float2bfloat16_rn(vv[j]);
                __nv_bfloat16 h1 = __float2bfloat16_rn(vv[j + 1]);
                __nv_bfloat16 l0 = __float2bfloat16_rn(vv[j] - __bfloat162float(h0));
                __nv_bfloat16 l1 = __float2bfloat16_rn(vv[j + 1] - __bfloat162float(h1));
                *(__nv_bfloat162*)(ahi + e + j) = __nv_bfloat162(h0, h1);
                *(__nv_bfloat162*)(alo + e + j) = __nv_bfloat162(l0, l1);
                __nv_bfloat16 g0 = __float2bfloat16_rn(wv[j]);
                __nv_bfloat16 g1 = __float2bfloat16_rn(wv[j + 1]);
                __nv_bfloat16 m0 = __float2bfloat16_rn(wv[j] - __bfloat162float(g0));
                __nv_bfloat16 m1 = __float2bfloat16_rn(wv[j + 1] - __bfloat162float(g1));
                *(__nv_bfloat162*)(bhi + e + j) = __nv_bfloat162(g0, g1);
                *(__nv_bfloat162*)(blo + e + j) = __nv_bfloat162(m0, m1);
            }
        }
    };

    ldg_tile(0);
    cvt_sts(0, true);
    __syncthreads();

    for (int kt = 0; kt < 32; ++kt) {
        const int s = kt & 1;
        if (kt + 1 < 32) ldg_tile(kt + 1);

        const uint32_t ahiB = s0 + (s * 4 + 0) * TILE_E * 2;
        const uint32_t aloB = s0 + (s * 4 + 1) * TILE_E * 2;
        const uint32_t bhiB = s0 + (s * 4 + 2) * TILE_E * 2;
        const uint32_t bloB = s0 + (s * 4 + 3) * TILE_E * 2;

#pragma unroll
        for (int ks = 0; ks < 2; ++ks) {
            const uint32_t k0b = ks * 32;                       // 16 bf16 = 32B
            // ---- A fragments (hi & lo) ----
            uint32_t ah[2][4], al[2][4];
            {
                const int arow_l = (lane & 15);
                const uint32_t acol = k0b + ((lane >> 4) << 4); // +16B for k8 half
#pragma unroll
                for (int mf = 0; mf < 2; ++mf) {
                    uint32_t off = (uint32_t)(warp_m + mf * 16 + arow_l) * 80 + acol;
                    LDSM4(ah[mf][0], ah[mf][1], ah[mf][2], ah[mf][3], ahiB + off);
                    LDSM4(al[mf][0], al[mf][1], al[mf][2], al[mf][3], aloB + off);
                }
            }
            // ---- B fragment pairs + MMA ----
            const int brow_l = (lane & 7) + ((lane >> 4) << 3);
            const uint32_t bcol = k0b + (((lane >> 3) & 1) << 4);
#pragma unroll
            for (int pair = 0; pair < 4; ++pair) {
                uint32_t boff = (uint32_t)(warp_n + pair * 16 + brow_l) * 80 + bcol;
                uint32_t bh[4], bo[4];
                LDSM4(bh[0], bh[1], bh[2], bh[3], bhiB + boff);
                LDSM4(bo[0], bo[1], bo[2], bo[3], bloB + boff);
#pragma unroll
                for (int mf = 0; mf < 2; ++mf)
#pragma unroll
                    for (int nfl = 0; nfl < 2; ++nfl) {
                        int nf = pair * 2 + nfl;
                        MMA_BF16(acc[mf][nf], ah[mf], bh[nfl * 2], bh[nfl * 2 + 1]);
                        MMA_BF16(acc[mf][nf], al[mf], bh[nfl * 2], bh[nfl * 2 + 1]);
                        MMA_BF16(acc[mf][nf], ah[mf], bo[nfl * 2], bo[nfl * 2 + 1]);
                    }
            }
        }
        if (kt + 1 < 32) cvt_sts((kt + 1) & 1, (kt + 1) < 16);
        __syncthreads();
    }

    // ---- epilogue: + bias, write to gmem -----------------------------------
#pragma unroll
    for (int mf = 0; mf < 2; ++mf) {
#pragma unroll
        for (int nf = 0; nf < 8; ++nf) {
            int m = row0 + warp_m + mf * 16 + (lane >> 2);
            int c = col0 + warp_n + nf * 8 + 2 * (lane & 3);
            float2 bb = *(const float2*)&bl[c];
            if (m < N) {
                float2 o = make_float2(acc[mf][nf][0] + bb.x, acc[mf][nf][1] + bb.y);
                *(float2*)&out[(size_t)m * DD + c] = o;
            }
            if (m + 8 < N) {
                float2 o = make_float2(acc[mf][nf][2] + bb.x, acc[mf][nf][3] + bb.y);
                *(float2*)&out[(size_t)(m + 8) * DD + c] = o;
            }
        }
    }
}

// -------- 1. zero scratch ---------------------------------------------------
__global__ void zero_kernel() {
    const size_t stride = (size_t)gridDim.x * blockDim.x;
    const size_t i = (size_t)blockIdx.x * blockDim.x + threadIdx.x;
    const size_t total4 = (size_t)NN * DD / 4;
    float4 z = make_float4(0.f, 0.f, 0.f, 0.f);
    for (size_t idx = i; idx < total4; idx += stride)
        ((float4*)g_agg)[idx] = z;
    if (i < NN) g_cnt[i] = 0;
    if (i < DD) { g_colsum[i] = 0.f; g_colsumsq[i] = 0.f; }
}

// -------- 2. edge scatter-add -----------------------------------------------
__global__ __launch_bounds__(256) void agg_kernel(
    const float* __restrict__ x, const int* __restrict__ ei, int E)
{
    long long t = (long long)blockIdx.x * blockDim.x + threadIdx.x;
    int e = (int)(t >> 7);
    if (e >= E) return;
    int c = ((int)t & 127) * 4;
    int src = __ldg(&ei[e]);
    int dst = __ldg(&ei[E + e]);
    float4 v = *(const float4*)&x[(size_t)src * DD + c];
    float* a = &g_agg[(size_t)dst * DD + c];
    atomicAdd(a + 0, v.x);
    atomicAdd(a + 1, v.y);
    atomicAdd(a + 2, v.z);
    atomicAdd(a + 3, v.w);
    if (c == 0) atomicAdd(&g_cnt[dst], 1);
}

// -------- 5. per-column sum / sumsq -----------------------------------------
__global__ void colstats_kernel(const float* __restrict__ h, int N) {
    int c = blockIdx.x * blockDim.x + threadIdx.x;
    int chunk = (N + gridDim.y - 1) / gridDim.y;
    int r0 = blockIdx.y * chunk;
    int r1 = min(r0 + chunk, N);
    float s = 0.f, sq = 0.f;
    for (int i = r0; i < r1; ++i) {
        float v = h[(size_t)i * DD + c];
        s += v;
        sq = fmaf(v, v, sq);
    }
    atomicAdd(&g_colsum[c], s);
    atomicAdd(&g_colsumsq[c], sq);
}

// -------- 6. finalize stats --------------------------------------------------
__global__ void stats_kernel(int N) {
    int c = threadIdx.x;
    float invn = 1.0f / (float)N;
    float mu = g_colsum[c] * invn;
    float var = g_colsumsq[c] * invn - mu * mu;
    g_mu[c] = mu;
    g_rstd[c] = rsqrtf(var + EPS);
}

// -------- 7. BN + relu + residual (in-place on h) ---------------------------
__global__ __launch_bounds__(256) void final_kernel(
    const float* __restrict__ x, const float* __restrict__ gamma,
    const float* __restrict__ beta, float* __restrict__ out, int N)
{
    size_t idx = (size_t)blockIdx.x * blockDim.x + threadIdx.x;
    size_t total4 = (size_t)N * DD / 4;
    if (idx >= total4) return;
    int c = (int)((idx * 4) & (DD - 1));
    float4 h  = ((float4*)out)[idx];
    float4 xv = ((const float4*)x)[idx];
    float4 mu = *(const float4*)&g_mu[c];
    float4 rs = *(const float4*)&g_rstd[c];
    float4 ga = *(const float4*)&gamma[c];
    float4 be = *(const float4*)&beta[c];
    float4 o;
    o.x = fmaxf(fmaf((h.x - mu.x) * rs.x, ga.x, be.x), 0.f) + xv.x;
    o.y = fmaxf(fmaf((h.y - mu.y) * rs.y, ga.y, be.y), 0.f) + xv.y;
    o.z = fmaxf(fmaf((h.z - mu.z) * rs.z, ga.z, be.z), 0.f) + xv.z;
    o.w = fmaxf(fmaf((h.w - mu.w) * rs.w, ga.w, be.w), 0.f) + xv.w;
    ((float4*)out)[idx] = o;
}

// ---------------------------------------------------------------------------
extern "C" void kernel_launch(void* const* d_in, const int* in_sizes, int n_in,
                              void* d_out, int out_size)
{
    const float* x  = (const float*)d_in[0];
    const int*   ei = (const int*)d_in[1];
    const float* Wl = (const float*)d_in[2];
    const float* bl = (const float*)d_in[3];
    const float* Wr = (const float*)d_in[4];
    const float* ga = (const float*)d_in[5];
    const float* be = (const float*)d_in[6];
    float* out = (float*)d_out;

    int N = in_sizes[0] / DD;
    int E = in_sizes[1] / 2;

    zero_kernel<<<256, 256>>>();

    long long work = (long long)E * 128;
    agg_kernel<<<(int)((work + 255) / 256), 256>>>(x, ei, E);

    static int smem_set = 0;
    if (!smem_set) {
        cudaFuncSetAttribute(gemm_mma, cudaFuncAttributeMaxDynamicSharedMemorySize,
                             SMEM_BYTES);
        smem_set = 1;
    }
    dim3 ggrid(DD / BN, (N + BM - 1) / BM);
    gemm_mma<<<ggrid, 256, SMEM_BYTES>>>(x, Wl, Wr, bl, out, N);

    dim3 cgrid(DD / 128, 128);
    colstats_kernel<<<cgrid, 128>>>(out, N);

    stats_kernel<<<1, DD>>>(N);

    size_t tot4 = (size_t)N * DD / 4;
    final_kernel<<<(int)((tot4 + 255) / 256), 256>>>(x, ga, be, out, N);
}

// round 4
// speedup vs baseline: 2.6414x; 1.5562x over previous
#include <cuda_runtime.h>
#include <cuda_bf16.h>
#include <cstdint>

#define NN 50000
#define EE 400000
#define DD 512
#define EPS 1e-5f

// -------- scratch (static __device__; no cudaMalloc allowed) ----------------
__device__ float g_agg[(size_t)NN * DD];   // mean-aggregated features
__device__ int   g_cnt[NN];
__device__ int   g_off[NN + 1];
__device__ int   g_woff[NN];
__device__ int   g_eidx[EE];
__device__ float g_colsum[DD];
__device__ float g_colsumsq[DD];
__device__ float g_mu[DD];
__device__ float g_rstd[DD];

// -------- helpers ------------------------------------------------------------
__device__ __forceinline__ uint32_t smem_u32(const void* p) {
    uint32_t a;
    asm("{ .reg .u64 t; cvta.to.shared.u64 t, %1; cvt.u32.u64 %0, t; }"
        : "=r"(a) : "l"(p));
    return a;
}

#define LDSM4(r0, r1, r2, r3, addr) \
    asm volatile("ldmatrix.sync.aligned.m8n8.x4.shared.b16 {%0,%1,%2,%3}, [%4];" \
        : "=r"(r0), "=r"(r1), "=r"(r2), "=r"(r3) : "r"(addr))

#define MMA_BF16(d, a, b0, b1) \
    asm volatile("mma.sync.aligned.m16n8k16.row.col.f32.bf16.bf16.f32 " \
        "{%0,%1,%2,%3}, {%4,%5,%6,%7}, {%8,%9}, {%0,%1,%2,%3};" \
        : "+f"((d)[0]), "+f"((d)[1]), "+f"((d)[2]), "+f"((d)[3]) \
        : "r"((a)[0]), "r"((a)[1]), "r"((a)[2]), "r"((a)[3]), "r"(b0), "r"(b1))

// tile config
#define BM 128
#define BN 128
#define BK 32
#define ROWSTR 40                 // bf16 elems per smem row (80 B, pad for LDSM)
#define TILE_E (128 * ROWSTR)
#define SMEM_BYTES (2 * 4 * TILE_E * 2)   // 81920

// ======================= CSR build + gather aggregation ======================

// 0. zero the small counters
__global__ void zero_small() {
    int i = blockIdx.x * blockDim.x + threadIdx.x;
    if (i < NN) g_cnt[i] = 0;
    if (i < DD) { g_colsum[i] = 0.f; g_colsumsq[i] = 0.f; }
}

// 1. histogram of destination degree
__global__ __launch_bounds__(256) void hist_kernel(const int* __restrict__ ei, int E) {
    int e = blockIdx.x * blockDim.x + threadIdx.x;
    if (e < E) atomicAdd(&g_cnt[__ldg(&ei[E + e])], 1);
}

// 2. single-block exclusive scan -> g_off, g_woff
__global__ __launch_bounds__(1024) void scan_kernel() {
    __shared__ int tsum[1024];
    const int CH = (NN + 1023) / 1024;        // 49
    int t = threadIdx.x;
    int beg = t * CH, end = min(beg + CH, NN);
    int s = 0;
    for (int i = beg; i < end; ++i) s += g_cnt[i];
    tsum[t] = s;
    __syncthreads();
    for (int d = 1; d < 1024; d <<= 1) {
        int v = (t >= d) ? tsum[t - d] : 0;
        __syncthreads();
        tsum[t] += v;
        __syncthreads();
    }
    int excl = (t == 0) ? 0 : tsum[t - 1];
    for (int i = beg; i < end; ++i) {
        int c = g_cnt[i];
        g_off[i] = excl;
        g_woff[i] = excl;
        excl += c;
    }
    if (end == NN && beg < NN) g_off[NN] = excl;
    if (t == 1023) g_off[NN] = tsum[1023];
}

// 3. scatter src ids into CSR slots
__global__ __launch_bounds__(256) void fill_kernel(const int* __restrict__ ei, int E) {
    int e = blockIdx.x * blockDim.x + threadIdx.x;
    if (e >= E) return;
    int src = __ldg(&ei[e]);
    int dst = __ldg(&ei[E + e]);
    int pos = atomicAdd(&g_woff[dst], 1);
    g_eidx[pos] = src;
}

// 4. gather-reduce: one warp per node, writes mean directly
__global__ __launch_bounds__(256) void gather_kernel(const float* __restrict__ x, int N) {
    int warp = (blockIdx.x * blockDim.x + threadIdx.x) >> 5;
    if (warp >= N) return;
    int lane = threadIdx.x & 31;
    int beg = g_off[warp], end = g_off[warp + 1];

    float4 acc0 = make_float4(0.f, 0.f, 0.f, 0.f);
    float4 acc1 = acc0, acc2 = acc0, acc3 = acc0;

    int e = beg;
    for (; e + 2 <= end; e += 2) {
        int s0 = __ldg(&g_eidx[e]);
        int s1 = __ldg(&g_eidx[e + 1]);
        const float4* r0 = (const float4*)&x[(size_t)s0 * DD];
        const float4* r1 = (const float4*)&x[(size_t)s1 * DD];
        float4 a0 = r0[lane], a1 = r0[lane + 32], a2 = r0[lane + 64], a3 = r0[lane + 96];
        float4 b0 = r1[lane], b1 = r1[lane + 32], b2 = r1[lane + 64], b3 = r1[lane + 96];
        acc0.x += a0.x + b0.x; acc0.y += a0.y + b0.y; acc0.z += a0.z + b0.z; acc0.w += a0.w + b0.w;
        acc1.x += a1.x + b1.x; acc1.y += a1.y + b1.y; acc1.z += a1.z + b1.z; acc1.w += a1.w + b1.w;
        acc2.x += a2.x + b2.x; acc2.y += a2.y + b2.y; acc2.z += a2.z + b2.z; acc2.w += a2.w + b2.w;
        acc3.x += a3.x + b3.x; acc3.y += a3.y + b3.y; acc3.z += a3.z + b3.z; acc3.w += a3.w + b3.w;
    }
    if (e < end) {
        int s0 = __ldg(&g_eidx[e]);
        const float4* r0 = (const float4*)&x[(size_t)s0 * DD];
        float4 a0 = r0[lane], a1 = r0[lane + 32], a2 = r0[lane + 64], a3 = r0[lane + 96];
        acc0.x += a0.x; acc0.y += a0.y; acc0.z += a0.z; acc0.w += a0.w;
        acc1.x += a1.x; acc1.y += a1.y; acc1.z += a1.z; acc1.w += a1.w;
        acc2.x += a2.x; acc2.y += a2.y; acc2.z += a2.z; acc2.w += a2.w;
        acc3.x += a3.x; acc3.y += a3.y; acc3.z += a3.z; acc3.w += a3.w;
    }
    float inv = 1.0f / (float)max(end - beg, 1);
    acc0.x *= inv; acc0.y *= inv; acc0.z *= inv; acc0.w *= inv;
    acc1.x *= inv; acc1.y *= inv; acc1.z *= inv; acc1.w *= inv;
    acc2.x *= inv; acc2.y *= inv; acc2.z *= inv; acc2.w *= inv;
    acc3.x *= inv; acc3.y *= inv; acc3.z *= inv; acc3.w *= inv;
    float4* dst = (float4*)&g_agg[(size_t)warp * DD];
    dst[lane] = acc0; dst[lane + 32] = acc1; dst[lane + 64] = acc2; dst[lane + 96] = acc3;
}

// ======================= bf16-split tensor GEMM ==============================
// h = mean_agg @ Wl^T + x @ Wr^T + bl
__global__ __launch_bounds__(256, 1) void gemm_mma(
    const float* __restrict__ x, const float* __restrict__ Wl,
    const float* __restrict__ Wr, const float* __restrict__ bl,
    float* __restrict__ out, int N)
{
    extern __shared__ __nv_bfloat16 sm[];
    const uint32_t s0 = smem_u32(sm);
    const int tid = threadIdx.x;
    const int lane = tid & 31, wid = tid >> 5;
    const int row0 = blockIdx.y * BM;
    const int col0 = blockIdx.x * BN;
    const int warp_m = (wid >> 1) * 32;
    const int warp_n = (wid & 1) * 64;

    float acc[2][8][4];
#pragma unroll
    for (int mf = 0; mf < 2; ++mf)
#pragma unroll
        for (int nf = 0; nf < 8; ++nf)
#pragma unroll
            for (int i = 0; i < 4; ++i) acc[mf][nf][i] = 0.f;

    float4 sa[4], sb[4];

    auto ldg_tile = [&](int kt) {
        const int k0 = (kt & 15) * BK;
        const float* A = (kt < 16) ? g_agg : x;
        const float* W = (kt < 16) ? Wl : Wr;
#pragma unroll
        for (int it = 0; it < 4; ++it) {
            int idx = it * 256 + tid;
            int r = idx >> 3, c4 = idx & 7;
            int rg = row0 + r;
            sa[it] = (rg < N) ? *(const float4*)&A[(size_t)rg * DD + k0 + c4 * 4]
                              : make_float4(0.f, 0.f, 0.f, 0.f);
            sb[it] = *(const float4*)&W[(size_t)(col0 + r) * DD + k0 + c4 * 4];
        }
    };

    auto cvt_sts = [&](int s) {
        __nv_bfloat16* ahi = sm + (s * 4 + 0) * TILE_E;
        __nv_bfloat16* alo = sm + (s * 4 + 1) * TILE_E;
        __nv_bfloat16* bhi = sm + (s * 4 + 2) * TILE_E;
        __nv_bfloat16* blo = sm + (s * 4 + 3) * TILE_E;
#pragma unroll
        for (int it = 0; it < 4; ++it) {
            int idx = it * 256 + tid;
            int r = idx >> 3, c4 = idx & 7;
            int e = r * ROWSTR + c4 * 4;
            float4 v = sa[it];
            float vv[4] = {v.x, v.y, v.z, v.w};
            float4 w = sb[it];
            float wv[4] = {w.x, w.y, w.z, w.w};
#pragma unroll
            for (int j = 0; j < 4; j += 2) {
                __nv_bfloat16 h0 = __float2bfloat16_rn(vv[j]);
                __nv_bfloat16 h1 = __float2bfloat16_rn(vv[j + 1]);
                __nv_bfloat16 l0 = __float2bfloat16_rn(vv[j] - __bfloat162float(h0));
                __nv_bfloat16 l1 = __float2bfloat16_rn(vv[j + 1] - __bfloat162float(h1));
                *(__nv_bfloat162*)(ahi + e + j) = __nv_bfloat162(h0, h1);
                *(__nv_bfloat162*)(alo + e + j) = __nv_bfloat162(l0, l1);
                __nv_bfloat16 g0 = __float2bfloat16_rn(wv[j]);
                __nv_bfloat16 g1 = __float2bfloat16_rn(wv[j + 1]);
                __nv_bfloat16 m0 = __float2bfloat16_rn(wv[j] - __bfloat162float(g0));
                __nv_bfloat16 m1 = __float2bfloat16_rn(wv[j + 1] - __bfloat162float(g1));
                *(__nv_bfloat162*)(bhi + e + j) = __nv_bfloat162(g0, g1);
                *(__nv_bfloat162*)(blo + e + j) = __nv_bfloat162(m0, m1);
            }
        }
    };

    ldg_tile(0);
    cvt_sts(0);
    __syncthreads();

    for (int kt = 0; kt < 32; ++kt) {
        const int s = kt & 1;
        if (kt + 1 < 32) ldg_tile(kt + 1);

        const uint32_t ahiB = s0 + (s * 4 + 0) * TILE_E * 2;
        const uint32_t aloB = s0 + (s * 4 + 1) * TILE_E * 2;
        const uint32_t bhiB = s0 + (s * 4 + 2) * TILE_E * 2;
        const uint32_t bloB = s0 + (s * 4 + 3) * TILE_E * 2;

#pragma unroll
        for (int ks = 0; ks < 2; ++ks) {
            const uint32_t k0b = ks * 32;
            uint32_t ah[2][4], al[2][4];
            {
                const int arow_l = (lane & 15);
                const uint32_t acol = k0b + ((lane >> 4) << 4);
#pragma unroll
                for (int mf = 0; mf < 2; ++mf) {
                    uint32_t off = (uint32_t)(warp_m + mf * 16 + arow_l) * 80 + acol;
                    LDSM4(ah[mf][0], ah[mf][1], ah[mf][2], ah[mf][3], ahiB + off);
                    LDSM4(al[mf][0], al[mf][1], al[mf][2], al[mf][3], aloB + off);
                }
            }
            const int brow_l = (lane & 7) + ((lane >> 4) << 3);
            const uint32_t bcol = k0b + (((lane >> 3) & 1) << 4);
#pragma unroll
            for (int pair = 0; pair < 4; ++pair) {
                uint32_t boff = (uint32_t)(warp_n + pair * 16 + brow_l) * 80 + bcol;
                uint32_t bh[4], bo[4];
                LDSM4(bh[0], bh[1], bh[2], bh[3], bhiB + boff);
                LDSM4(bo[0], bo[1], bo[2], bo[3], bloB + boff);
#pragma unroll
                for (int mf = 0; mf < 2; ++mf)
#pragma unroll
                    for (int nfl = 0; nfl < 2; ++nfl) {
                        int nf = pair * 2 + nfl;
                        MMA_BF16(acc[mf][nf], ah[mf], bh[nfl * 2], bh[nfl * 2 + 1]);
                        MMA_BF16(acc[mf][nf], al[mf], bh[nfl * 2], bh[nfl * 2 + 1]);
                        MMA_BF16(acc[mf][nf], ah[mf], bo[nfl * 2], bo[nfl * 2 + 1]);
                    }
            }
        }
        if (kt + 1 < 32) cvt_sts((kt + 1) & 1);
        __syncthreads();
    }

#pragma unroll
    for (int mf = 0; mf < 2; ++mf) {
#pragma unroll
        for (int nf = 0; nf < 8; ++nf) {
            int m = row0 + warp_m + mf * 16 + (lane >> 2);
            int c = col0 + warp_n + nf * 8 + 2 * (lane & 3);
            float2 bb = *(const float2*)&bl[c];
            if (m < N) {
                float2 o = make_float2(acc[mf][nf][0] + bb.x, acc[mf][nf][1] + bb.y);
                *(float2*)&out[(size_t)m * DD + c] = o;
            }
            if (m + 8 < N) {
                float2 o = make_float2(acc[mf][nf][2] + bb.x, acc[mf][nf][3] + bb.y);
                *(float2*)&out[(size_t)(m + 8) * DD + c] = o;
            }
        }
    }
}

// ======================= BN stats + epilogue =================================
__global__ void colstats_kernel(const float* __restrict__ h, int N) {
    int c = blockIdx.x * blockDim.x + threadIdx.x;
    int chunk = (N + gridDim.y - 1) / gridDim.y;
    int r0 = blockIdx.y * chunk;
    int r1 = min(r0 + chunk, N);
    float s = 0.f, sq = 0.f;
    for (int i = r0; i < r1; ++i) {
        float v = h[(size_t)i * DD + c];
        s += v;
        sq = fmaf(v, v, sq);
    }
    atomicAdd(&g_colsum[c], s);
    atomicAdd(&g_colsumsq[c], sq);
}

__global__ void stats_kernel(int N) {
    int c = threadIdx.x;
    float invn = 1.0f / (float)N;
    float mu = g_colsum[c] * invn;
    float var = g_colsumsq[c] * invn - mu * mu;
    g_mu[c] = mu;
    g_rstd[c] = rsqrtf(var + EPS);
}

__global__ __launch_bounds__(256) void final_kernel(
    const float* __restrict__ x, const float* __restrict__ gamma,
    const float* __restrict__ beta, float* __restrict__ out, int N)
{
    size_t idx = (size_t)blockIdx.x * blockDim.x + threadIdx.x;
    size_t total4 = (size_t)N * DD / 4;
    if (idx >= total4) return;
    int c = (int)((idx * 4) & (DD - 1));
    float4 h  = ((float4*)out)[idx];
    float4 xv = ((const float4*)x)[idx];
    float4 mu = *(const float4*)&g_mu[c];
    float4 rs = *(const float4*)&g_rstd[c];
    float4 ga = *(const float4*)&gamma[c];
    float4 be = *(const float4*)&beta[c];
    float4 o;
    o.x = fmaxf(fmaf((h.x - mu.x) * rs.x, ga.x, be.x), 0.f) + xv.x;
    o.y = fmaxf(fmaf((h.y - mu.y) * rs.y, ga.y, be.y), 0.f) + xv.y;
    o.z = fmaxf(fmaf((h.z - mu.z) * rs.z, ga.z, be.z), 0.f) + xv.z;
    o.w = fmaxf(fmaf((h.w - mu.w) * rs.w, ga.w, be.w), 0.f) + xv.w;
    ((float4*)out)[idx] = o;
}

// ---------------------------------------------------------------------------
extern "C" void kernel_launch(void* const* d_in, const int* in_sizes, int n_in,
                              void* d_out, int out_size)
{
    const float* x  = (const float*)d_in[0];
    const int*   ei = (const int*)d_in[1];
    const float* Wl = (const float*)d_in[2];
    const float* bl = (const float*)d_in[3];
    const float* Wr = (const float*)d_in[4];
    const float* ga = (const float*)d_in[5];
    const float* be = (const float*)d_in[6];
    float* out = (float*)d_out;

    int N = in_sizes[0] / DD;
    int E = in_sizes[1] / 2;

    zero_small<<<(NN + 255) / 256, 256>>>();
    hist_kernel<<<(E + 255) / 256, 256>>>(ei, E);
    scan_kernel<<<1, 1024>>>();
    fill_kernel<<<(E + 255) / 256, 256>>>(ei, E);
    gather_kernel<<<(N + 7) / 8, 256>>>(x, N);

    static int smem_set = 0;
    if (!smem_set) {
        cudaFuncSetAttribute(gemm_mma, cudaFuncAttributeMaxDynamicSharedMemorySize,
                             SMEM_BYTES);
        smem_set = 1;
    }
    dim3 ggrid(DD / BN, (N + BM - 1) / BM);
    gemm_mma<<<ggrid, 256, SMEM_BYTES>>>(x, Wl, Wr, bl, out, N);

    dim3 cgrid(DD / 128, 128);
    colstats_kernel<<<cgrid, 128>>>(out, N);

    stats_kernel<<<1, DD>>>(N);

    size_t tot4 = (size_t)N * DD / 4;
    final_kernel<<<(int)((tot4 + 255) / 256), 256>>>(x, ga, be, out, N);
}

// round 5
// speedup vs baseline: 2.7046x; 1.0239x over previous
#include <cuda_runtime.h>
#include <cuda_bf16.h>
#include <cstdint>

#define NN 50000
#define EE 400000
#define DD 512
#define EPS 1e-5f

// -------- scratch (static __device__; no cudaMalloc allowed) ----------------
__device__ __nv_bfloat16 g_aghi[(size_t)NN * DD];
__device__ __nv_bfloat16 g_aglo[(size_t)NN * DD];
__device__ __nv_bfloat16 g_xhi[(size_t)NN * DD];
__device__ __nv_bfloat16 g_xlo[(size_t)NN * DD];
__device__ __nv_bfloat16 g_wbhi[512 * 1024];   // [n][k] k<512:Wl, k>=512:Wr
__device__ __nv_bfloat16 g_wblo[512 * 1024];
__device__ int   g_cnt[NN];
__device__ int   g_off[NN + 1];
__device__ int   g_woff[NN];
__device__ int   g_eidx[EE];
__device__ float g_colsum[DD];
__device__ float g_colsumsq[DD];
__device__ float g_mu[DD];
__device__ float g_rstd[DD];

// -------- helpers ------------------------------------------------------------
__device__ __forceinline__ uint32_t smem_u32(const void* p) {
    uint32_t a;
    asm("{ .reg .u64 t; cvta.to.shared.u64 t, %1; cvt.u32.u64 %0, t; }"
        : "=r"(a) : "l"(p));
    return a;
}

#define LDSM4(r0, r1, r2, r3, addr) \
    asm volatile("ldmatrix.sync.aligned.m8n8.x4.shared.b16 {%0,%1,%2,%3}, [%4];" \
        : "=r"(r0), "=r"(r1), "=r"(r2), "=r"(r3) : "r"(addr))

#define MMA_BF16(d, a, b0, b1) \
    asm volatile("mma.sync.aligned.m16n8k16.row.col.f32.bf16.bf16.f32 " \
        "{%0,%1,%2,%3}, {%4,%5,%6,%7}, {%8,%9}, {%0,%1,%2,%3};" \
        : "+f"((d)[0]), "+f"((d)[1]), "+f"((d)[2]), "+f"((d)[3]) \
        : "r"((a)[0]), "r"((a)[1]), "r"((a)[2]), "r"((a)[3]), "r"(b0), "r"(b1))

#define CP16(dst, src, nb) \
    asm volatile("cp.async.cg.shared.global [%0], [%1], 16, %2;" \
        :: "r"(dst), "l"(src), "r"(nb))
#define CP_COMMIT() asm volatile("cp.async.commit_group;" ::: "memory")
#define CP_WAIT1()  asm volatile("cp.async.wait_group 1;" ::: "memory")
#define CP_WAIT0()  asm volatile("cp.async.wait_group 0;" ::: "memory")

// tile config
#define BM 128
#define BN 128
#define STAGE_B 40960      // {Ahi,Alo,Bhi,Blo} x 128 rows x 80 B
#define SMEM_BYTES (2 * STAGE_B)

// ======================= pre-conversion kernels ==============================
__global__ __launch_bounds__(256) void conv_w(
    const float* __restrict__ Wl, const float* __restrict__ Wr)
{
    int i = blockIdx.x * blockDim.x + threadIdx.x;
    if (i >= 512 * 1024) return;
    int n = i >> 10, k = i & 1023;
    float v = (k < 512) ? Wl[n * 512 + k] : Wr[n * 512 + (k - 512)];
    __nv_bfloat16 h = __float2bfloat16_rn(v);
    g_wbhi[i] = h;
    g_wblo[i] = __float2bfloat16_rn(v - __bfloat162float(h));
}

__global__ __launch_bounds__(256) void conv_x(const float* __restrict__ x, int N) {
    size_t i = (size_t)blockIdx.x * blockDim.x + threadIdx.x;
    size_t tot = (size_t)N * DD / 4;
    if (i >= tot) return;
    float4 v = ((const float4*)x)[i];
    __nv_bfloat16 h0 = __float2bfloat16_rn(v.x), h1 = __float2bfloat16_rn(v.y);
    __nv_bfloat16 h2 = __float2bfloat16_rn(v.z), h3 = __float2bfloat16_rn(v.w);
    __nv_bfloat162 hi0(h0, h1), hi1(h2, h3);
    __nv_bfloat162 lo0(__float2bfloat16_rn(v.x - __bfloat162float(h0)),
                       __float2bfloat16_rn(v.y - __bfloat162float(h1)));
    __nv_bfloat162 lo1(__float2bfloat16_rn(v.z - __bfloat162float(h2)),
                       __float2bfloat16_rn(v.w - __bfloat162float(h3)));
    ((__nv_bfloat162*)g_xhi)[i * 2] = hi0; ((__nv_bfloat162*)g_xhi)[i * 2 + 1] = hi1;
    ((__nv_bfloat162*)g_xlo)[i * 2] = lo0; ((__nv_bfloat162*)g_xlo)[i * 2 + 1] = lo1;
}

// ======================= CSR build + gather aggregation ======================
__global__ void zero_small() {
    int i = blockIdx.x * blockDim.x + threadIdx.x;
    if (i < NN) g_cnt[i] = 0;
    if (i < DD) { g_colsum[i] = 0.f; g_colsumsq[i] = 0.f; }
}

__global__ __launch_bounds__(256) void hist_kernel(const int* __restrict__ ei, int E) {
    int e = blockIdx.x * blockDim.x + threadIdx.x;
    if (e < E) atomicAdd(&g_cnt[__ldg(&ei[E + e])], 1);
}

__global__ __launch_bounds__(1024) void scan_kernel() {
    __shared__ int tsum[1024];
    const int CH = (NN + 1023) / 1024;
    int t = threadIdx.x;
    int beg = t * CH, end = min(beg + CH, NN);
    int s = 0;
    for (int i = beg; i < end; ++i) s += g_cnt[i];
    tsum[t] = s;
    __syncthreads();
    for (int d = 1; d < 1024; d <<= 1) {
        int v = (t >= d) ? tsum[t - d] : 0;
        __syncthreads();
        tsum[t] += v;
        __syncthreads();
    }
    int excl = (t == 0) ? 0 : tsum[t - 1];
    for (int i = beg; i < end; ++i) {
        int c = g_cnt[i];
        g_off[i] = excl;
        g_woff[i] = excl;
        excl += c;
    }
    if (t == 1023) g_off[NN] = tsum[1023];
}

__global__ __launch_bounds__(256) void fill_kernel(const int* __restrict__ ei, int E) {
    int e = blockIdx.x * blockDim.x + threadIdx.x;
    if (e >= E) return;
    int src = __ldg(&ei[e]);
    int dst = __ldg(&ei[E + e]);
    int pos = atomicAdd(&g_woff[dst], 1);
    g_eidx[pos] = src;
}

// gather-reduce: one warp per node -> mean, stored as bf16 hi/lo
__global__ __launch_bounds__(256) void gather_kernel(const float* __restrict__ x, int N) {
    int warp = (blockIdx.x * blockDim.x + threadIdx.x) >> 5;
    if (warp >= N) return;
    int lane = threadIdx.x & 31;
    int beg = g_off[warp], end = g_off[warp + 1];

    float4 acc0 = make_float4(0.f, 0.f, 0.f, 0.f);
    float4 acc1 = acc0, acc2 = acc0, acc3 = acc0;

    int e = beg;
    for (; e + 2 <= end; e += 2) {
        int s0 = __ldg(&g_eidx[e]);
        int s1 = __ldg(&g_eidx[e + 1]);
        const float4* r0 = (const float4*)&x[(size_t)s0 * DD];
        const float4* r1 = (const float4*)&x[(size_t)s1 * DD];
        float4 a0 = r0[lane], a1 = r0[lane + 32], a2 = r0[lane + 64], a3 = r0[lane + 96];
        float4 b0 = r1[lane], b1 = r1[lane + 32], b2 = r1[lane + 64], b3 = r1[lane + 96];
        acc0.x += a0.x + b0.x; acc0.y += a0.y + b0.y; acc0.z += a0.z + b0.z; acc0.w += a0.w + b0.w;
        acc1.x += a1.x + b1.x; acc1.y += a1.y + b1.y; acc1.z += a1.z + b1.z; acc1.w += a1.w + b1.w;
        acc2.x += a2.x + b2.x; acc2.y += a2.y + b2.y; acc2.z += a2.z + b2.z; acc2.w += a2.w + b2.w;
        acc3.x += a3.x + b3.x; acc3.y += a3.y + b3.y; acc3.z += a3.z + b3.z; acc3.w += a3.w + b3.w;
    }
    if (e < end) {
        int s0 = __ldg(&g_eidx[e]);
        const float4* r0 = (const float4*)&x[(size_t)s0 * DD];
        float4 a0 = r0[lane], a1 = r0[lane + 32], a2 = r0[lane + 64], a3 = r0[lane + 96];
        acc0.x += a0.x; acc0.y += a0.y; acc0.z += a0.z; acc0.w += a0.w;
        acc1.x += a1.x; acc1.y += a1.y; acc1.z += a1.z; acc1.w += a1.w;
        acc2.x += a2.x; acc2.y += a2.y; acc2.z += a2.z; acc2.w += a2.w;
        acc3.x += a3.x; acc3.y += a3.y; acc3.z += a3.z; acc3.w += a3.w;
    }
    float inv = 1.0f / (float)max(end - beg, 1);
    float4 ac[4] = {acc0, acc1, acc2, acc3};
#pragma unroll
    for (int q = 0; q < 4; ++q) {
        float4 v = ac[q];
        v.x *= inv; v.y *= inv; v.z *= inv; v.w *= inv;
        __nv_bfloat16 h0 = __float2bfloat16_rn(v.x), h1 = __float2bfloat16_rn(v.y);
        __nv_bfloat16 h2 = __float2bfloat16_rn(v.z), h3 = __float2bfloat16_rn(v.w);
        __nv_bfloat162 hi0(h0, h1), hi1(h2, h3);
        __nv_bfloat162 lo0(__float2bfloat16_rn(v.x - __bfloat162float(h0)),
                           __float2bfloat16_rn(v.y - __bfloat162float(h1)));
        __nv_bfloat162 lo1(__float2bfloat16_rn(v.z - __bfloat162float(h2)),
                           __float2bfloat16_rn(v.w - __bfloat162float(h3)));
        size_t o2 = ((size_t)warp * DD + (size_t)(lane + q * 32) * 4) / 2;
        ((__nv_bfloat162*)g_aghi)[o2] = hi0; ((__nv_bfloat162*)g_aghi)[o2 + 1] = hi1;
        ((__nv_bfloat162*)g_aglo)[o2] = lo0; ((__nv_bfloat162*)g_aglo)[o2 + 1] = lo1;
    }
}

// ======================= bf16-split tensor GEMM (cp.async) ===================
// h = mean_agg @ Wl^T + x @ Wr^T + bl
__global__ __launch_bounds__(256, 2) void gemm_mma(
    const __nv_bfloat16* __restrict__ dummy,   // keeps signature flexible
    const float* __restrict__ bl, float* __restrict__ out, int N)
{
    extern __shared__ char sm[];
    const uint32_t s0 = smem_u32(sm);
    const int tid = threadIdx.x;
    const int lane = tid & 31, wid = tid >> 5;
    const int row0 = blockIdx.y * BM;
    const int col0 = blockIdx.x * BN;
    const int warp_m = (wid >> 1) * 32;
    const int warp_n = (wid & 1) * 64;

    float acc[2][8][4];
#pragma unroll
    for (int mf = 0; mf < 2; ++mf)
#pragma unroll
        for (int nf = 0; nf < 8; ++nf)
#pragma unroll
            for (int i = 0; i < 4; ++i) acc[mf][nf][i] = 0.f;

    auto issue_chunk = [&](int kt) {
        const int s = kt & 1;
        const uint32_t sb = s0 + s * STAGE_B;
        const int kk = (kt & 15) * 32;
        const __nv_bfloat16* Ah = (kt < 16) ? g_aghi : g_xhi;
        const __nv_bfloat16* Al = (kt < 16) ? g_aglo : g_xlo;
#pragma unroll
        for (int it = 0; it < 2; ++it) {
            int idx = it * 256 + tid;            // 0..511
            int r = idx >> 2, c16 = idx & 3;
            int rg = row0 + r;
            int nb = (rg < N) ? 16 : 0;
            int rc = min(rg, N - 1);
            const __nv_bfloat16* sH = Ah + (size_t)rc * DD + kk + c16 * 8;
            const __nv_bfloat16* sL = Al + (size_t)rc * DD + kk + c16 * 8;
            uint32_t d = sb + (uint32_t)r * 80 + c16 * 16;
            CP16(d, sH, nb);
            CP16(d + 10240, sL, nb);
        }
#pragma unroll
        for (int it = 0; it < 2; ++it) {
            int idx = it * 256 + tid;
            int r = idx >> 2, c16 = idx & 3;
            const __nv_bfloat16* sH = g_wbhi + (size_t)(col0 + r) * 1024 + kt * 32 + c16 * 8;
            const __nv_bfloat16* sL = g_wblo + (size_t)(col0 + r) * 1024 + kt * 32 + c16 * 8;
            uint32_t d = sb + 20480 + (uint32_t)r * 80 + c16 * 16;
            CP16(d, sH, 16);
            CP16(d + 10240, sL, 16);
        }
    };

    issue_chunk(0); CP_COMMIT();
    issue_chunk(1); CP_COMMIT();
    CP_WAIT1();
    __syncthreads();

    for (int kt = 0; kt < 32; ++kt) {
        const int s = kt & 1;
        const uint32_t ahiB = s0 + s * STAGE_B;
        const uint32_t aloB = ahiB + 10240;
        const uint32_t bhiB = ahiB + 20480;
        const uint32_t bloB = ahiB + 30720;

#pragma unroll
        for (int ks = 0; ks < 2; ++ks) {
            const uint32_t k0b = ks * 32;
            uint32_t ah[2][4], al[2][4];
            {
                const int arow_l = (lane & 15);
                const uint32_t acol = k0b + ((lane >> 4) << 4);
#pragma unroll
                for (int mf = 0; mf < 2; ++mf) {
                    uint32_t off = (uint32_t)(warp_m + mf * 16 + arow_l) * 80 + acol;
                    LDSM4(ah[mf][0], ah[mf][1], ah[mf][2], ah[mf][3], ahiB + off);
                    LDSM4(al[mf][0], al[mf][1], al[mf][2], al[mf][3], aloB + off);
                }
            }
            const int brow_l = (lane & 7) + ((lane >> 4) << 3);
            const uint32_t bcol = k0b + (((lane >> 3) & 1) << 4);
#pragma unroll
            for (int pair = 0; pair < 4; ++pair) {
                uint32_t boff = (uint32_t)(warp_n + pair * 16 + brow_l) * 80 + bcol;
                uint32_t bh[4], bo[4];
                LDSM4(bh[0], bh[1], bh[2], bh[3], bhiB + boff);
                LDSM4(bo[0], bo[1], bo[2], bo[3], bloB + boff);
#pragma unroll
                for (int mf = 0; mf < 2; ++mf)
#pragma unroll
                    for (int nfl = 0; nfl < 2; ++nfl) {
                        int nf = pair * 2 + nfl;
                        MMA_BF16(acc[mf][nf], ah[mf], bh[nfl * 2], bh[nfl * 2 + 1]);
                        MMA_BF16(acc[mf][nf], al[mf], bh[nfl * 2], bh[nfl * 2 + 1]);
                        MMA_BF16(acc[mf][nf], ah[mf], bo[nfl * 2], bo[nfl * 2 + 1]);
                    }
            }
        }
        __syncthreads();                       // all warps done reading stage s
        if (kt + 2 < 32) { issue_chunk(kt + 2); CP_COMMIT(); CP_WAIT1(); }
        else             { CP_WAIT0(); }
        __syncthreads();                       // next stage visible to all
    }

#pragma unroll
    for (int mf = 0; mf < 2; ++mf) {
#pragma unroll
        for (int nf = 0; nf < 8; ++nf) {
            int m = row0 + warp_m + mf * 16 + (lane >> 2);
            int c = col0 + warp_n + nf * 8 + 2 * (lane & 3);
            float2 bb = *(const float2*)&bl[c];
            if (m < N) {
                float2 o = make_float2(acc[mf][nf][0] + bb.x, acc[mf][nf][1] + bb.y);
                *(float2*)&out[(size_t)m * DD + c] = o;
            }
            if (m + 8 < N) {
                float2 o = make_float2(acc[mf][nf][2] + bb.x, acc[mf][nf][3] + bb.y);
                *(float2*)&out[(size_t)(m + 8) * DD + c] = o;
            }
        }
    }
}

// ======================= BN stats + epilogue =================================
__global__ void colstats_kernel(const float* __restrict__ h, int N) {
    int c = blockIdx.x * blockDim.x + threadIdx.x;
    int chunk = (N + gridDim.y - 1) / gridDim.y;
    int r0 = blockIdx.y * chunk;
    int r1 = min(r0 + chunk, N);
    float s = 0.f, sq = 0.f;
    for (int i = r0; i < r1; ++i) {
        float v = h[(size_t)i * DD + c];
        s += v;
        sq = fmaf(v, v, sq);
    }
    atomicAdd(&g_colsum[c], s);
    atomicAdd(&g_colsumsq[c], sq);
}

__global__ void stats_kernel(int N) {
    int c = threadIdx.x;
    float invn = 1.0f / (float)N;
    float mu = g_colsum[c] * invn;
    float var = g_colsumsq[c] * invn - mu * mu;
    g_mu[c] = mu;
    g_rstd[c] = rsqrtf(var + EPS);
}

__global__ __launch_bounds__(256) void final_kernel(
    const float* __restrict__ x, const float* __restrict__ gamma,
    const float* __restrict__ beta, float* __restrict__ out, int N)
{
    size_t idx = (size_t)blockIdx.x * blockDim.x + threadIdx.x;
    size_t total4 = (size_t)N * DD / 4;
    if (idx >= total4) return;
    int c = (int)((idx * 4) & (DD - 1));
    float4 h  = ((float4*)out)[idx];
    float4 xv = ((const float4*)x)[idx];
    float4 mu = *(const float4*)&g_mu[c];
    float4 rs = *(const float4*)&g_rstd[c];
    float4 ga = *(const float4*)&gamma[c];
    float4 be = *(const float4*)&beta[c];
    float4 o;
    o.x = fmaxf(fmaf((h.x - mu.x) * rs.x, ga.x, be.x), 0.f) + xv.x;
    o.y = fmaxf(fmaf((h.y - mu.y) * rs.y, ga.y, be.y), 0.f) + xv.y;
    o.z = fmaxf(fmaf((h.z - mu.z) * rs.z, ga.z, be.z), 0.f) + xv.z;
    o.w = fmaxf(fmaf((h.w - mu.w) * rs.w, ga.w, be.w), 0.f) + xv.w;
    ((float4*)out)[idx] = o;
}

// ---------------------------------------------------------------------------
extern "C" void kernel_launch(void* const* d_in, const int* in_sizes, int n_in,
                              void* d_out, int out_size)
{
    const float* x  = (const float*)d_in[0];
    const int*   ei = (const int*)d_in[1];
    const float* Wl = (const float*)d_in[2];
    const float* bl = (const float*)d_in[3];
    const float* Wr = (const float*)d_in[4];
    const float* ga = (const float*)d_in[5];
    const float* be = (const float*)d_in[6];
    float* out = (float*)d_out;

    int N = in_sizes[0] / DD;
    int E = in_sizes[1] / 2;

    zero_small<<<(NN + 255) / 256, 256>>>();
    hist_kernel<<<(E + 255) / 256, 256>>>(ei, E);
    scan_kernel<<<1, 1024>>>();
    fill_kernel<<<(E + 255) / 256, 256>>>(ei, E);
    gather_kernel<<<(N + 7) / 8, 256>>>(x, N);

    conv_w<<<(512 * 1024 + 255) / 256, 256>>>(Wl, Wr);
    size_t xtot4 = (size_t)N * DD / 4;
    conv_x<<<(int)((xtot4 + 255) / 256), 256>>>(x, N);

    static int smem_set = 0;
    if (!smem_set) {
        cudaFuncSetAttribute(gemm_mma, cudaFuncAttributeMaxDynamicSharedMemorySize,
                             SMEM_BYTES);
        smem_set = 1;
    }
    dim3 ggrid(DD / BN, (N + BM - 1) / BM);
    gemm_mma<<<ggrid, 256, SMEM_BYTES>>>(nullptr, bl, out, N);

    dim3 cgrid(DD / 128, 128);
    colstats_kernel<<<cgrid, 128>>>(out, N);

    stats_kernel<<<1, DD>>>(N);

    size_t tot4 = (size_t)N * DD / 4;
    final_kernel<<<(int)((tot4 + 255) / 256), 256>>>(x, ga, be, out, N);
}

// round 6
// speedup vs baseline: 3.4911x; 1.2908x over previous
#include <cuda_runtime.h>
#include <cuda_fp16.h>
#include <cstdint>

#define NN 50000
#define EE 400000
#define DD 512
#define EPS 1e-5f

// -------- scratch (static __device__; no cudaMalloc allowed) ----------------
__device__ __half g_aghi[(size_t)NN * DD];
__device__ __half g_aglo[(size_t)NN * DD];
__device__ __half g_xhi[(size_t)NN * DD];
__device__ __half g_xlo[(size_t)NN * DD];
__device__ __half g_whi[512 * 1024];       // [n][k] k<512:Wl, k>=512:Wr
__device__ int   g_cnt[NN];
__device__ int   g_off[NN + 1];
__device__ int   g_woff[NN];
__device__ int   g_eidx[EE];
__device__ float g_colsum[DD];
__device__ float g_colsumsq[DD];
__device__ float g_mu[DD];
__device__ float g_rstd[DD];

// -------- helpers ------------------------------------------------------------
__device__ __forceinline__ uint32_t smem_u32(const void* p) {
    uint32_t a;
    asm("{ .reg .u64 t; cvta.to.shared.u64 t, %1; cvt.u32.u64 %0, t; }"
        : "=r"(a) : "l"(p));
    return a;
}

#define LDSM4(r0, r1, r2, r3, addr) \
    asm volatile("ldmatrix.sync.aligned.m8n8.x4.shared.b16 {%0,%1,%2,%3}, [%4];" \
        : "=r"(r0), "=r"(r1), "=r"(r2), "=r"(r3) : "r"(addr))

#define MMA_F16(d, a, b0, b1) \
    asm volatile("mma.sync.aligned.m16n8k16.row.col.f32.f16.f16.f32 " \
        "{%0,%1,%2,%3}, {%4,%5,%6,%7}, {%8,%9}, {%0,%1,%2,%3};" \
        : "+f"((d)[0]), "+f"((d)[1]), "+f"((d)[2]), "+f"((d)[3]) \
        : "r"((a)[0]), "r"((a)[1]), "r"((a)[2]), "r"((a)[3]), "r"(b0), "r"(b1))

#define CP16(dst, src, nb) \
    asm volatile("cp.async.cg.shared.global [%0], [%1], 16, %2;" \
        :: "r"(dst), "l"(src), "r"(nb))
#define CP_COMMIT() asm volatile("cp.async.commit_group;" ::: "memory")
#define CP_WAIT1()  asm volatile("cp.async.wait_group 1;" ::: "memory")
#define CP_WAIT0()  asm volatile("cp.async.wait_group 0;" ::: "memory")

// tile config
#define BM 128
#define BN 128
#define STAGE_B 30720      // {Ahi,Alo,Bhi} x 128 rows x 80 B
#define SMEM_BYTES (2 * STAGE_B)

// ======================= pre-conversion kernels ==============================
__global__ __launch_bounds__(256) void conv_w(
    const float* __restrict__ Wl, const float* __restrict__ Wr)
{
    int i = blockIdx.x * blockDim.x + threadIdx.x;
    if (i >= 512 * 1024) return;
    int n = i >> 10, k = i & 1023;
    float v = (k < 512) ? Wl[n * 512 + k] : Wr[n * 512 + (k - 512)];
    g_whi[i] = __float2half_rn(v);
}

__global__ __launch_bounds__(256) void conv_x(const float* __restrict__ x, int N) {
    size_t i = (size_t)blockIdx.x * blockDim.x + threadIdx.x;
    size_t tot = (size_t)N * DD / 4;
    if (i >= tot) return;
    float4 v = ((const float4*)x)[i];
    __half h0 = __float2half_rn(v.x), h1 = __float2half_rn(v.y);
    __half h2 = __float2half_rn(v.z), h3 = __float2half_rn(v.w);
    __half2 hi0(h0, h1), hi1(h2, h3);
    __half2 lo0(__float2half_rn(v.x - __half2float(h0)),
                __float2half_rn(v.y - __half2float(h1)));
    __half2 lo1(__float2half_rn(v.z - __half2float(h2)),
                __float2half_rn(v.w - __half2float(h3)));
    ((__half2*)g_xhi)[i * 2] = hi0; ((__half2*)g_xhi)[i * 2 + 1] = hi1;
    ((__half2*)g_xlo)[i * 2] = lo0; ((__half2*)g_xlo)[i * 2 + 1] = lo1;
}

// ======================= CSR build + gather aggregation ======================
__global__ void zero_small() {
    int i = blockIdx.x * blockDim.x + threadIdx.x;
    if (i < NN) g_cnt[i] = 0;
    if (i < DD) { g_colsum[i] = 0.f; g_colsumsq[i] = 0.f; }
}

__global__ __launch_bounds__(256) void hist_kernel(const int* __restrict__ ei, int E) {
    int e = blockIdx.x * blockDim.x + threadIdx.x;
    if (e < E) atomicAdd(&g_cnt[__ldg(&ei[E + e])], 1);
}

__global__ __launch_bounds__(1024) void scan_kernel() {
    __shared__ int tsum[1024];
    const int CH = (NN + 1023) / 1024;
    int t = threadIdx.x;
    int beg = t * CH, end = min(beg + CH, NN);
    int s = 0;
    for (int i = beg; i < end; ++i) s += g_cnt[i];
    tsum[t] = s;
    __syncthreads();
    for (int d = 1; d < 1024; d <<= 1) {
        int v = (t >= d) ? tsum[t - d] : 0;
        __syncthreads();
        tsum[t] += v;
        __syncthreads();
    }
    int excl = (t == 0) ? 0 : tsum[t - 1];
    for (int i = beg; i < end; ++i) {
        int c = g_cnt[i];
        g_off[i] = excl;
        g_woff[i] = excl;
        excl += c;
    }
    if (t == 1023) g_off[NN] = tsum[1023];
}

__global__ __launch_bounds__(256) void fill_kernel(const int* __restrict__ ei, int E) {
    int e = blockIdx.x * blockDim.x + threadIdx.x;
    if (e >= E) return;
    int src = __ldg(&ei[e]);
    int dst = __ldg(&ei[E + e]);
    int pos = atomicAdd(&g_woff[dst], 1);
    g_eidx[pos] = src;
}

// gather-reduce: one warp per node -> mean, stored as fp16 hi/lo
__global__ __launch_bounds__(256) void gather_kernel(const float* __restrict__ x, int N) {
    int warp = (blockIdx.x * blockDim.x + threadIdx.x) >> 5;
    if (warp >= N) return;
    int lane = threadIdx.x & 31;
    int beg = g_off[warp], end = g_off[warp + 1];

    float4 acc0 = make_float4(0.f, 0.f, 0.f, 0.f);
    float4 acc1 = acc0, acc2 = acc0, acc3 = acc0;

    int e = beg;
    for (; e + 2 <= end; e += 2) {
        int s0 = __ldg(&g_eidx[e]);
        int s1 = __ldg(&g_eidx[e + 1]);
        const float4* r0 = (const float4*)&x[(size_t)s0 * DD];
        const float4* r1 = (const float4*)&x[(size_t)s1 * DD];
        float4 a0 = r0[lane], a1 = r0[lane + 32], a2 = r0[lane + 64], a3 = r0[lane + 96];
        float4 b0 = r1[lane], b1 = r1[lane + 32], b2 = r1[lane + 64], b3 = r1[lane + 96];
        acc0.x += a0.x + b0.x; acc0.y += a0.y + b0.y; acc0.z += a0.z + b0.z; acc0.w += a0.w + b0.w;
        acc1.x += a1.x + b1.x; acc1.y += a1.y + b1.y; acc1.z += a1.z + b1.z; acc1.w += a1.w + b1.w;
        acc2.x += a2.x + b2.x; acc2.y += a2.y + b2.y; acc2.z += a2.z + b2.z; acc2.w += a2.w + b2.w;
        acc3.x += a3.x + b3.x; acc3.y += a3.y + b3.y; acc3.z += a3.z + b3.z; acc3.w += a3.w + b3.w;
    }
    if (e < end) {
        int s0 = __ldg(&g_eidx[e]);
        const float4* r0 = (const float4*)&x[(size_t)s0 * DD];
        float4 a0 = r0[lane], a1 = r0[lane + 32], a2 = r0[lane + 64], a3 = r0[lane + 96];
        acc0.x += a0.x; acc0.y += a0.y; acc0.z += a0.z; acc0.w += a0.w;
        acc1.x += a1.x; acc1.y += a1.y; acc1.z += a1.z; acc1.w += a1.w;
        acc2.x += a2.x; acc2.y += a2.y; acc2.z += a2.z; acc2.w += a2.w;
        acc3.x += a3.x; acc3.y += a3.y; acc3.z += a3.z; acc3.w += a3.w;
    }
    float inv = 1.0f / (float)max(end - beg, 1);
    float4 ac[4] = {acc0, acc1, acc2, acc3};
#pragma unroll
    for (int q = 0; q < 4; ++q) {
        float4 v = ac[q];
        v.x *= inv; v.y *= inv; v.z *= inv; v.w *= inv;
        __half h0 = __float2half_rn(v.x), h1 = __float2half_rn(v.y);
        __half h2 = __float2half_rn(v.z), h3 = __float2half_rn(v.w);
        __half2 hi0(h0, h1), hi1(h2, h3);
        __half2 lo0(__float2half_rn(v.x - __half2float(h0)),
                    __float2half_rn(v.y - __half2float(h1)));
        __half2 lo1(__float2half_rn(v.z - __half2float(h2)),
                    __float2half_rn(v.w - __half2float(h3)));
        size_t o2 = ((size_t)warp * DD + (size_t)(lane + q * 32) * 4) / 2;
        ((__half2*)g_aghi)[o2] = hi0; ((__half2*)g_aghi)[o2 + 1] = hi1;
        ((__half2*)g_aglo)[o2] = lo0; ((__half2*)g_aglo)[o2 + 1] = lo1;
    }
}

// ======================= fp16 2-term tensor GEMM (cp.async) ==================
// h = mean_agg @ Wl^T + x @ Wr^T + bl ; fused per-column sum/sumsq
__global__ __launch_bounds__(256, 2) void gemm_mma(
    const float* __restrict__ bl, float* __restrict__ out, int N)
{
    extern __shared__ char sm[];
    const uint32_t s0 = smem_u32(sm);
    const int tid = threadIdx.x;
    const int lane = tid & 31, wid = tid >> 5;
    const int row0 = blockIdx.y * BM;
    const int col0 = blockIdx.x * BN;
    const int warp_m = (wid >> 1) * 32;
    const int warp_n = (wid & 1) * 64;

    float acc[2][8][4];
#pragma unroll
    for (int mf = 0; mf < 2; ++mf)
#pragma unroll
        for (int nf = 0; nf < 8; ++nf)
#pragma unroll
            for (int i = 0; i < 4; ++i) acc[mf][nf][i] = 0.f;

    auto issue_chunk = [&](int kt) {
        const int s = kt & 1;
        const uint32_t sb = s0 + s * STAGE_B;
        const int kk = (kt & 15) * 32;
        const __half* Ah = (kt < 16) ? g_aghi : g_xhi;
        const __half* Al = (kt < 16) ? g_aglo : g_xlo;
#pragma unroll
        for (int it = 0; it < 2; ++it) {
            int idx = it * 256 + tid;            // 0..511
            int r = idx >> 2, c16 = idx & 3;
            int rg = row0 + r;
            int nb = (rg < N) ? 16 : 0;
            int rc = min(rg, N - 1);
            const __half* sH = Ah + (size_t)rc * DD + kk + c16 * 8;
            const __half* sL = Al + (size_t)rc * DD + kk + c16 * 8;
            uint32_t d = sb + (uint32_t)r * 80 + c16 * 16;
            CP16(d, sH, nb);
            CP16(d + 10240, sL, nb);
        }
        {
            int idx = tid;                       // 0..255 -> half of B rows
#pragma unroll
            for (int it = 0; it < 2; ++it) {
                int id2 = it * 256 + idx;
                int r = id2 >> 2, c16 = id2 & 3;
                const __half* sH = g_whi + (size_t)(col0 + r) * 1024 + kt * 32 + c16 * 8;
                uint32_t d = sb + 20480 + (uint32_t)r * 80 + c16 * 16;
                CP16(d, sH, 16);
            }
        }
    };

    issue_chunk(0); CP_COMMIT();
    issue_chunk(1); CP_COMMIT();
    CP_WAIT1();
    __syncthreads();

    for (int kt = 0; kt < 32; ++kt) {
        const int s = kt & 1;
        const uint32_t ahiB = s0 + s * STAGE_B;
        const uint32_t aloB = ahiB + 10240;
        const uint32_t bhiB = ahiB + 20480;

#pragma unroll
        for (int ks = 0; ks < 2; ++ks) {
            const uint32_t k0b = ks * 32;
            uint32_t ah[2][4], al[2][4];
            {
                const int arow_l = (lane & 15);
                const uint32_t acol = k0b + ((lane >> 4) << 4);
#pragma unroll
                for (int mf = 0; mf < 2; ++mf) {
                    uint32_t off = (uint32_t)(warp_m + mf * 16 + arow_l) * 80 + acol;
                    LDSM4(ah[mf][0], ah[mf][1], ah[mf][2], ah[mf][3], ahiB + off);
                    LDSM4(al[mf][0], al[mf][1], al[mf][2], al[mf][3], aloB + off);
                }
            }
            const int brow_l = (lane & 7) + ((lane >> 4) << 3);
            const uint32_t bcol = k0b + (((lane >> 3) & 1) << 4);
#pragma unroll
            for (int pair = 0; pair < 4; ++pair) {
                uint32_t boff = (uint32_t)(warp_n + pair * 16 + brow_l) * 80 + bcol;
                uint32_t bh[4];
                LDSM4(bh[0], bh[1], bh[2], bh[3], bhiB + boff);
#pragma unroll
                for (int mf = 0; mf < 2; ++mf)
#pragma unroll
                    for (int nfl = 0; nfl < 2; ++nfl) {
                        int nf = pair * 2 + nfl;
                        MMA_F16(acc[mf][nf], ah[mf], bh[nfl * 2], bh[nfl * 2 + 1]);
                        MMA_F16(acc[mf][nf], al[mf], bh[nfl * 2], bh[nfl * 2 + 1]);
                    }
            }
        }
        __syncthreads();                       // all warps done reading stage s
        if (kt + 2 < 32) { issue_chunk(kt + 2); CP_COMMIT(); CP_WAIT1(); }
        else             { CP_WAIT0(); }
        __syncthreads();                       // next stage visible to all
    }

    // ---- epilogue: +bias, store, fused column sum/sumsq --------------------
#pragma unroll
    for (int nf = 0; nf < 8; ++nf) {
        int c = col0 + warp_n + nf * 8 + 2 * (lane & 3);
        float2 bb = *(const float2*)&bl[c];
        float sA = 0.f, sB = 0.f, qA = 0.f, qB = 0.f;
#pragma unroll
        for (int mf = 0; mf < 2; ++mf) {
            int m = row0 + warp_m + mf * 16 + (lane >> 2);
            if (m < N) {
                float o0 = acc[mf][nf][0] + bb.x, o1 = acc[mf][nf][1] + bb.y;
                *(float2*)&out[(size_t)m * DD + c] = make_float2(o0, o1);
                sA += o0; sB += o1; qA += o0 * o0; qB += o1 * o1;
            }
            if (m + 8 < N) {
                float o0 = acc[mf][nf][2] + bb.x, o1 = acc[mf][nf][3] + bb.y;
                *(float2*)&out[(size_t)(m + 8) * DD + c] = make_float2(o0, o1);
                sA += o0; sB += o1; qA += o0 * o0; qB += o1 * o1;
            }
        }
#pragma unroll
        for (int d = 4; d < 32; d <<= 1) {
            sA += __shfl_xor_sync(0xffffffffu, sA, d);
            sB += __shfl_xor_sync(0xffffffffu, sB, d);
            qA += __shfl_xor_sync(0xffffffffu, qA, d);
            qB += __shfl_xor_sync(0xffffffffu, qB, d);
        }
        if (lane < 4) {
            atomicAdd(&g_colsum[c], sA);
            atomicAdd(&g_colsum[c + 1], sB);
            atomicAdd(&g_colsumsq[c], qA);
            atomicAdd(&g_colsumsq[c + 1], qB);
        }
    }
}

// ======================= BN stats + epilogue =================================
__global__ void stats_kernel(int N) {
    int c = threadIdx.x;
    float invn = 1.0f / (float)N;
    float mu = g_colsum[c] * invn;
    float var = g_colsumsq[c] * invn - mu * mu;
    g_mu[c] = mu;
    g_rstd[c] = rsqrtf(var + EPS);
}

__global__ __launch_bounds__(256) void final_kernel(
    const float* __restrict__ x, const float* __restrict__ gamma,
    const float* __restrict__ beta, float* __restrict__ out, int N)
{
    size_t idx = (size_t)blockIdx.x * blockDim.x + threadIdx.x;
    size_t total4 = (size_t)N * DD / 4;
    if (idx >= total4) return;
    int c = (int)((idx * 4) & (DD - 1));
    float4 h  = ((float4*)out)[idx];
    float4 xv = ((const float4*)x)[idx];
    float4 mu = *(const float4*)&g_mu[c];
    float4 rs = *(const float4*)&g_rstd[c];
    float4 ga = *(const float4*)&gamma[c];
    float4 be = *(const float4*)&beta[c];
    float4 o;
    o.x = fmaxf(fmaf((h.x - mu.x) * rs.x, ga.x, be.x), 0.f) + xv.x;
    o.y = fmaxf(fmaf((h.y - mu.y) * rs.y, ga.y, be.y), 0.f) + xv.y;
    o.z = fmaxf(fmaf((h.z - mu.z) * rs.z, ga.z, be.z), 0.f) + xv.z;
    o.w = fmaxf(fmaf((h.w - mu.w) * rs.w, ga.w, be.w), 0.f) + xv.w;
    ((float4*)out)[idx] = o;
}

// ---------------------------------------------------------------------------
extern "C" void kernel_launch(void* const* d_in, const int* in_sizes, int n_in,
                              void* d_out, int out_size)
{
    const float* x  = (const float*)d_in[0];
    const int*   ei = (const int*)d_in[1];
    const float* Wl = (const float*)d_in[2];
    const float* bl = (const float*)d_in[3];
    const float* Wr = (const float*)d_in[4];
    const float* ga = (const float*)d_in[5];
    const float* be = (const float*)d_in[6];
    float* out = (float*)d_out;

    int N = in_sizes[0] / DD;
    int E = in_sizes[1] / 2;

    zero_small<<<(NN + 255) / 256, 256>>>();
    hist_kernel<<<(E + 255) / 256, 256>>>(ei, E);
    scan_kernel<<<1, 1024>>>();
    fill_kernel<<<(E + 255) / 256, 256>>>(ei, E);
    gather_kernel<<<(N + 7) / 8, 256>>>(x, N);

    conv_w<<<(512 * 1024 + 255) / 256, 256>>>(Wl, Wr);
    size_t xtot4 = (size_t)N * DD / 4;
    conv_x<<<(int)((xtot4 + 255) / 256), 256>>>(x, N);

    static int smem_set = 0;
    if (!smem_set) {
        cudaFuncSetAttribute(gemm_mma, cudaFuncAttributeMaxDynamicSharedMemorySize,
                             SMEM_BYTES);
        smem_set = 1;
    }
    dim3 ggrid(DD / BN, (N + BM - 1) / BM);
    gemm_mma<<<ggrid, 256, SMEM_BYTES>>>(bl, out, N);

    stats_kernel<<<1, DD>>>(N);

    size_t tot4 = (size_t)N * DD / 4;
    final_kernel<<<(int)((tot4 + 255) / 256), 256>>>(x, ga, be, out, N);
}

// round 7
// speedup vs baseline: 4.8325x; 1.3842x over previous
#include <cuda_runtime.h>
#include <cuda_fp16.h>
#include <cstdint>

#define NN 50000
#define EE 400000
#define DD 512
#define EPS 1e-5f

// -------- scratch (static __device__; no cudaMalloc allowed) ----------------
__device__ __half g_ag[(size_t)NN * DD];   // mean-aggregated, fp16
__device__ __half g_xhi[(size_t)NN * DD];  // x, fp16
__device__ __half g_whi[512 * 1024];       // [n][k] k<512:Wl, k>=512:Wr
__device__ int   g_cnt[NN];
__device__ int   g_off[NN + 1];
__device__ int   g_woff[NN];
__device__ int   g_eidx[EE];
__device__ float g_colsum[DD];
__device__ float g_colsumsq[DD];
__device__ float g_mu[DD];
__device__ float g_rstd[DD];

// -------- helpers ------------------------------------------------------------
__device__ __forceinline__ uint32_t smem_u32(const void* p) {
    uint32_t a;
    asm("{ .reg .u64 t; cvta.to.shared.u64 t, %1; cvt.u32.u64 %0, t; }"
        : "=r"(a) : "l"(p));
    return a;
}

#define LDSM4(r0, r1, r2, r3, addr) \
    asm volatile("ldmatrix.sync.aligned.m8n8.x4.shared.b16 {%0,%1,%2,%3}, [%4];" \
        : "=r"(r0), "=r"(r1), "=r"(r2), "=r"(r3) : "r"(addr))

#define MMA_F16(d, a, b0, b1) \
    asm volatile("mma.sync.aligned.m16n8k16.row.col.f32.f16.f16.f32 " \
        "{%0,%1,%2,%3}, {%4,%5,%6,%7}, {%8,%9}, {%0,%1,%2,%3};" \
        : "+f"((d)[0]), "+f"((d)[1]), "+f"((d)[2]), "+f"((d)[3]) \
        : "r"((a)[0]), "r"((a)[1]), "r"((a)[2]), "r"((a)[3]), "r"(b0), "r"(b1))

#define CP16(dst, src, nb) \
    asm volatile("cp.async.cg.shared.global [%0], [%1], 16, %2;" \
        :: "r"(dst), "l"(src), "r"(nb))
#define CP_COMMIT() asm volatile("cp.async.commit_group;" ::: "memory")
#define CP_WAIT1()  asm volatile("cp.async.wait_group 1;" ::: "memory")
#define CP_WAIT0()  asm volatile("cp.async.wait_group 0;" ::: "memory")

// tile config
#define BM 128
#define BN 128
#define STAGE_B 20480      // {A,B} x 128 rows x 80 B
#define SMEM_BYTES (2 * STAGE_B)

// ======================= pre-conversion kernels ==============================
__global__ __launch_bounds__(256) void conv_w(
    const float* __restrict__ Wl, const float* __restrict__ Wr)
{
    int i = blockIdx.x * blockDim.x + threadIdx.x;
    if (i >= 512 * 1024) return;
    int n = i >> 10, k = i & 1023;
    float v = (k < 512) ? Wl[n * 512 + k] : Wr[n * 512 + (k - 512)];
    g_whi[i] = __float2half_rn(v);
}

__global__ __launch_bounds__(256) void conv_x(const float* __restrict__ x, int N) {
    size_t i = (size_t)blockIdx.x * blockDim.x + threadIdx.x;
    size_t tot = (size_t)N * DD / 4;
    if (i >= tot) return;
    float4 v = ((const float4*)x)[i];
    __half2 hi0(__float2half_rn(v.x), __float2half_rn(v.y));
    __half2 hi1(__float2half_rn(v.z), __float2half_rn(v.w));
    ((__half2*)g_xhi)[i * 2] = hi0;
    ((__half2*)g_xhi)[i * 2 + 1] = hi1;
}

// ======================= CSR build + gather aggregation ======================
__global__ void zero_small() {
    int i = blockIdx.x * blockDim.x + threadIdx.x;
    if (i < NN) g_cnt[i] = 0;
    if (i < DD) { g_colsum[i] = 0.f; g_colsumsq[i] = 0.f; }
}

__global__ __launch_bounds__(256) void hist_kernel(const int* __restrict__ ei, int E) {
    int e = blockIdx.x * blockDim.x + threadIdx.x;
    if (e < E) atomicAdd(&g_cnt[__ldg(&ei[E + e])], 1);
}

__global__ __launch_bounds__(1024) void scan_kernel() {
    __shared__ int tsum[1024];
    const int CH = (NN + 1023) / 1024;
    int t = threadIdx.x;
    int beg = t * CH, end = min(beg + CH, NN);
    int s = 0;
    for (int i = beg; i < end; ++i) s += g_cnt[i];
    tsum[t] = s;
    __syncthreads();
    for (int d = 1; d < 1024; d <<= 1) {
        int v = (t >= d) ? tsum[t - d] : 0;
        __syncthreads();
        tsum[t] += v;
        __syncthreads();
    }
    int excl = (t == 0) ? 0 : tsum[t - 1];
    for (int i = beg; i < end; ++i) {
        int c = g_cnt[i];
        g_off[i] = excl;
        g_woff[i] = excl;
        excl += c;
    }
    if (t == 1023) g_off[NN] = tsum[1023];
}

__global__ __launch_bounds__(256) void fill_kernel(const int* __restrict__ ei, int E) {
    int e = blockIdx.x * blockDim.x + threadIdx.x;
    if (e >= E) return;
    int src = __ldg(&ei[e]);
    int dst = __ldg(&ei[E + e]);
    int pos = atomicAdd(&g_woff[dst], 1);
    g_eidx[pos] = src;
}

// gather-reduce over fp16 x: one warp per node; fp32 accum; fp16 mean out.
// each lane owns 16 contiguous halfs (32 B = 2 uint4 loads per row).
__global__ __launch_bounds__(256) void gather_kernel(int N) {
    int warp = (blockIdx.x * blockDim.x + threadIdx.x) >> 5;
    if (warp >= N) return;
    int lane = threadIdx.x & 31;
    int beg = g_off[warp], end = g_off[warp + 1];

    float acc[16];
#pragma unroll
    for (int i = 0; i < 16; ++i) acc[i] = 0.f;

    int e = beg;
    for (; e + 2 <= end; e += 2) {
        int s0 = __ldg(&g_eidx[e]);
        int s1 = __ldg(&g_eidx[e + 1]);
        const uint4* r0 = (const uint4*)&g_xhi[(size_t)s0 * DD + lane * 16];
        const uint4* r1 = (const uint4*)&g_xhi[(size_t)s1 * DD + lane * 16];
        uint4 p0 = r0[0], p1 = r0[1], q0 = r1[0], q1 = r1[1];
        const __half2* hp0 = (const __half2*)&p0;
        const __half2* hp1 = (const __half2*)&p1;
        const __half2* hq0 = (const __half2*)&q0;
        const __half2* hq1 = (const __half2*)&q1;
#pragma unroll
        for (int j = 0; j < 4; ++j) {
            float2 a = __half22float2(hp0[j]), b = __half22float2(hq0[j]);
            acc[j * 2] += a.x + b.x; acc[j * 2 + 1] += a.y + b.y;
            float2 c = __half22float2(hp1[j]), d = __half22float2(hq1[j]);
            acc[8 + j * 2] += c.x + d.x; acc[8 + j * 2 + 1] += c.y + d.y;
        }
    }
    if (e < end) {
        int s0 = __ldg(&g_eidx[e]);
        const uint4* r0 = (const uint4*)&g_xhi[(size_t)s0 * DD + lane * 16];
        uint4 p0 = r0[0], p1 = r0[1];
        const __half2* hp0 = (const __half2*)&p0;
        const __half2* hp1 = (const __half2*)&p1;
#pragma unroll
        for (int j = 0; j < 4; ++j) {
            float2 a = __half22float2(hp0[j]);
            acc[j * 2] += a.x; acc[j * 2 + 1] += a.y;
            float2 c = __half22float2(hp1[j]);
            acc[8 + j * 2] += c.x; acc[8 + j * 2 + 1] += c.y;
        }
    }
    float inv = 1.0f / (float)max(end - beg, 1);
    uint4 o0, o1;
    __half2* ho0 = (__half2*)&o0;
    __half2* ho1 = (__half2*)&o1;
#pragma unroll
    for (int j = 0; j < 4; ++j) {
        ho0[j] = __floats2half2_rn(acc[j * 2] * inv, acc[j * 2 + 1] * inv);
        ho1[j] = __floats2half2_rn(acc[8 + j * 2] * inv, acc[8 + j * 2 + 1] * inv);
    }
    uint4* dst = (uint4*)&g_ag[(size_t)warp * DD + lane * 16];
    dst[0] = o0; dst[1] = o1;
}

// ======================= fp16 tensor GEMM (cp.async) =========================
// h = mean_agg @ Wl^T + x @ Wr^T + bl ; fused per-column sum/sumsq
__global__ __launch_bounds__(256, 2) void gemm_mma(
    const float* __restrict__ bl, float* __restrict__ out, int N)
{
    extern __shared__ char sm[];
    const uint32_t s0 = smem_u32(sm);
    const int tid = threadIdx.x;
    const int lane = tid & 31, wid = tid >> 5;
    const int row0 = blockIdx.y * BM;
    const int col0 = blockIdx.x * BN;
    const int warp_m = (wid >> 1) * 32;
    const int warp_n = (wid & 1) * 64;

    float acc[2][8][4];
#pragma unroll
    for (int mf = 0; mf < 2; ++mf)
#pragma unroll
        for (int nf = 0; nf < 8; ++nf)
#pragma unroll
            for (int i = 0; i < 4; ++i) acc[mf][nf][i] = 0.f;

    auto issue_chunk = [&](int kt) {
        const int s = kt & 1;
        const uint32_t sb = s0 + s * STAGE_B;
        const int kk = (kt & 15) * 32;
        const __half* Ah = (kt < 16) ? g_ag : g_xhi;
#pragma unroll
        for (int it = 0; it < 2; ++it) {
            int idx = it * 256 + tid;            // 0..511
            int r = idx >> 2, c16 = idx & 3;
            int rg = row0 + r;
            int nb = (rg < N) ? 16 : 0;
            int rc = min(rg, N - 1);
            const __half* sH = Ah + (size_t)rc * DD + kk + c16 * 8;
            uint32_t d = sb + (uint32_t)r * 80 + c16 * 16;
            CP16(d, sH, nb);
        }
#pragma unroll
        for (int it = 0; it < 2; ++it) {
            int idx = it * 256 + tid;
            int r = idx >> 2, c16 = idx & 3;
            const __half* sH = g_whi + (size_t)(col0 + r) * 1024 + kt * 32 + c16 * 8;
            uint32_t d = sb + 10240 + (uint32_t)r * 80 + c16 * 16;
            CP16(d, sH, 16);
        }
    };

    issue_chunk(0); CP_COMMIT();
    issue_chunk(1); CP_COMMIT();
    CP_WAIT1();
    __syncthreads();

    for (int kt = 0; kt < 32; ++kt) {
        const int s = kt & 1;
        const uint32_t ahiB = s0 + s * STAGE_B;
        const uint32_t bhiB = ahiB + 10240;

#pragma unroll
        for (int ks = 0; ks < 2; ++ks) {
            const uint32_t k0b = ks * 32;
            uint32_t ah[2][4];
            {
                const int arow_l = (lane & 15);
                const uint32_t acol = k0b + ((lane >> 4) << 4);
#pragma unroll
                for (int mf = 0; mf < 2; ++mf) {
                    uint32_t off = (uint32_t)(warp_m + mf * 16 + arow_l) * 80 + acol;
                    LDSM4(ah[mf][0], ah[mf][1], ah[mf][2], ah[mf][3], ahiB + off);
                }
            }
            const int brow_l = (lane & 7) + ((lane >> 4) << 3);
            const uint32_t bcol = k0b + (((lane >> 3) & 1) << 4);
#pragma unroll
            for (int pair = 0; pair < 4; ++pair) {
                uint32_t boff = (uint32_t)(warp_n + pair * 16 + brow_l) * 80 + bcol;
                uint32_t bh[4];
                LDSM4(bh[0], bh[1], bh[2], bh[3], bhiB + boff);
#pragma unroll
                for (int mf = 0; mf < 2; ++mf)
#pragma unroll
                    for (int nfl = 0; nfl < 2; ++nfl) {
                        int nf = pair * 2 + nfl;
                        MMA_F16(acc[mf][nf], ah[mf], bh[nfl * 2], bh[nfl * 2 + 1]);
                    }
            }
        }
        __syncthreads();                       // all warps done reading stage s
        if (kt + 2 < 32) { issue_chunk(kt + 2); CP_COMMIT(); CP_WAIT1(); }
        else             { CP_WAIT0(); }
        __syncthreads();                       // next stage visible to all
    }

    // ---- epilogue: +bias, store, fused column sum/sumsq --------------------
#pragma unroll
    for (int nf = 0; nf < 8; ++nf) {
        int c = col0 + warp_n + nf * 8 + 2 * (lane & 3);
        float2 bb = *(const float2*)&bl[c];
        float sA = 0.f, sB = 0.f, qA = 0.f, qB = 0.f;
#pragma unroll
        for (int mf = 0; mf < 2; ++mf) {
            int m = row0 + warp_m + mf * 16 + (lane >> 2);
            if (m < N) {
                float o0 = acc[mf][nf][0] + bb.x, o1 = acc[mf][nf][1] + bb.y;
                *(float2*)&out[(size_t)m * DD + c] = make_float2(o0, o1);
                sA += o0; sB += o1; qA += o0 * o0; qB += o1 * o1;
            }
            if (m + 8 < N) {
                float o0 = acc[mf][nf][2] + bb.x, o1 = acc[mf][nf][3] + bb.y;
                *(float2*)&out[(size_t)(m + 8) * DD + c] = make_float2(o0, o1);
                sA += o0; sB += o1; qA += o0 * o0; qB += o1 * o1;
            }
        }
#pragma unroll
        for (int d = 4; d < 32; d <<= 1) {
            sA += __shfl_xor_sync(0xffffffffu, sA, d);
            sB += __shfl_xor_sync(0xffffffffu, sB, d);
            qA += __shfl_xor_sync(0xffffffffu, qA, d);
            qB += __shfl_xor_sync(0xffffffffu, qB, d);
        }
        if (lane < 4) {
            atomicAdd(&g_colsum[c], sA);
            atomicAdd(&g_colsum[c + 1], sB);
            atomicAdd(&g_colsumsq[c], qA);
            atomicAdd(&g_colsumsq[c + 1], qB);
        }
    }
}

// ======================= BN stats + epilogue =================================
__global__ void stats_kernel(int N) {
    int c = threadIdx.x;
    float invn = 1.0f / (float)N;
    float mu = g_colsum[c] * invn;
    float var = g_colsumsq[c] * invn - mu * mu;
    g_mu[c] = mu;
    g_rstd[c] = rsqrtf(var + EPS);
}

__global__ __launch_bounds__(256) void final_kernel(
    const float* __restrict__ x, const float* __restrict__ gamma,
    const float* __restrict__ beta, float* __restrict__ out, int N)
{
    size_t idx = (size_t)blockIdx.x * blockDim.x + threadIdx.x;
    size_t total4 = (size_t)N * DD / 4;
    if (idx >= total4) return;
    int c = (int)((idx * 4) & (DD - 1));
    float4 h  = ((float4*)out)[idx];
    float4 xv = ((const float4*)x)[idx];
    float4 mu = *(const float4*)&g_mu[c];
    float4 rs = *(const float4*)&g_rstd[c];
    float4 ga = *(const float4*)&gamma[c];
    float4 be = *(const float4*)&beta[c];
    float4 o;
    o.x = fmaxf(fmaf((h.x - mu.x) * rs.x, ga.x, be.x), 0.f) + xv.x;
    o.y = fmaxf(fmaf((h.y - mu.y) * rs.y, ga.y, be.y), 0.f) + xv.y;
    o.z = fmaxf(fmaf((h.z - mu.z) * rs.z, ga.z, be.z), 0.f) + xv.z;
    o.w = fmaxf(fmaf((h.w - mu.w) * rs.w, ga.w, be.w), 0.f) + xv.w;
    ((float4*)out)[idx] = o;
}

// ---------------------------------------------------------------------------
extern "C" void kernel_launch(void* const* d_in, const int* in_sizes, int n_in,
                              void* d_out, int out_size)
{
    const float* x  = (const float*)d_in[0];
    const int*   ei = (const int*)d_in[1];
    const float* Wl = (const float*)d_in[2];
    const float* bl = (const float*)d_in[3];
    const float* Wr = (const float*)d_in[4];
    const float* ga = (const float*)d_in[5];
    const float* be = (const float*)d_in[6];
    float* out = (float*)d_out;

    int N = in_sizes[0] / DD;
    int E = in_sizes[1] / 2;

    zero_small<<<(NN + 255) / 256, 256>>>();
    hist_kernel<<<(E + 255) / 256, 256>>>(ei, E);
    scan_kernel<<<1, 1024>>>();
    fill_kernel<<<(E + 255) / 256, 256>>>(ei, E);

    size_t xtot4 = (size_t)N * DD / 4;
    conv_x<<<(int)((xtot4 + 255) / 256), 256>>>(x, N);
    conv_w<<<(512 * 1024 + 255) / 256, 256>>>(Wl, Wr);

    gather_kernel<<<(N + 7) / 8, 256>>>(N);

    static int smem_set = 0;
    if (!smem_set) {
        cudaFuncSetAttribute(gemm_mma, cudaFuncAttributeMaxDynamicSharedMemorySize,
                             SMEM_BYTES);
        smem_set = 1;
    }
    dim3 ggrid(DD / BN, (N + BM - 1) / BM);
    gemm_mma<<<ggrid, 256, SMEM_BYTES>>>(bl, out, N);

    stats_kernel<<<1, DD>>>(N);

    size_t tot4 = (size_t)N * DD / 4;
    final_kernel<<<(int)((tot4 + 255) / 256), 256>>>(x, ga, be, out, N);
}

// round 8
// speedup vs baseline: 4.9078x; 1.0156x over previous
#include <cuda_runtime.h>
#include <cuda_fp16.h>
#include <cstdint>

#define NN 50000
#define EE 400000
#define DD 512
#define EPS 1e-5f

// -------- scratch (static __device__; no cudaMalloc allowed) ----------------
__device__ __half g_ag[(size_t)NN * DD];   // mean-aggregated, fp16
__device__ __half g_xhi[(size_t)NN * DD];  // x, fp16
__device__ __half g_whi[512 * 1024];       // [n][k] k<512:Wl, k>=512:Wr
__device__ int   g_cnt[NN];
__device__ int   g_off[NN + 1];
__device__ int   g_woff[NN];
__device__ int   g_eidx[EE];
__device__ float g_colsum[DD];
__device__ float g_colsumsq[DD];
__device__ float g_mu[DD];
__device__ float g_rstd[DD];

// -------- helpers ------------------------------------------------------------
__device__ __forceinline__ uint32_t smem_u32(const void* p) {
    uint32_t a;
    asm("{ .reg .u64 t; cvta.to.shared.u64 t, %1; cvt.u32.u64 %0, t; }"
        : "=r"(a) : "l"(p));
    return a;
}

#define LDSM4(r0, r1, r2, r3, addr) \
    asm volatile("ldmatrix.sync.aligned.m8n8.x4.shared.b16 {%0,%1,%2,%3}, [%4];" \
        : "=r"(r0), "=r"(r1), "=r"(r2), "=r"(r3) : "r"(addr))

#define MMA_F16(d, a, b0, b1) \
    asm volatile("mma.sync.aligned.m16n8k16.row.col.f32.f16.f16.f32 " \
        "{%0,%1,%2,%3}, {%4,%5,%6,%7}, {%8,%9}, {%0,%1,%2,%3};" \
        : "+f"((d)[0]), "+f"((d)[1]), "+f"((d)[2]), "+f"((d)[3]) \
        : "r"((a)[0]), "r"((a)[1]), "r"((a)[2]), "r"((a)[3]), "r"(b0), "r"(b1))

#define CP16(dst, src, nb) \
    asm volatile("cp.async.cg.shared.global [%0], [%1], 16, %2;" \
        :: "r"(dst), "l"(src), "r"(nb))
#define CP_COMMIT() asm volatile("cp.async.commit_group;" ::: "memory")
#define CP_WAIT1()  asm volatile("cp.async.wait_group 1;" ::: "memory")
#define CP_WAIT0()  asm volatile("cp.async.wait_group 0;" ::: "memory")

// tile config
#define BM 128
#define BN 128
#define STAGE_B 20480      // {A,B} x 128 rows x 80 B
#define SMEM_BYTES (3 * STAGE_B)

// ======================= pre-conversion kernels ==============================
__global__ __launch_bounds__(256) void conv_w(
    const float* __restrict__ Wl, const float* __restrict__ Wr)
{
    int i = blockIdx.x * blockDim.x + threadIdx.x;
    if (i >= 512 * 1024) return;
    int n = i >> 10, k = i & 1023;
    float v = (k < 512) ? Wl[n * 512 + k] : Wr[n * 512 + (k - 512)];
    g_whi[i] = __float2half_rn(v);
}

__global__ __launch_bounds__(256) void conv_x(const float* __restrict__ x, int N) {
    size_t i = (size_t)blockIdx.x * blockDim.x + threadIdx.x;
    size_t tot = (size_t)N * DD / 4;
    if (i >= tot) return;
    float4 v = ((const float4*)x)[i];
    __half2 hi0(__float2half_rn(v.x), __float2half_rn(v.y));
    __half2 hi1(__float2half_rn(v.z), __float2half_rn(v.w));
    ((__half2*)g_xhi)[i * 2] = hi0;
    ((__half2*)g_xhi)[i * 2 + 1] = hi1;
}

// ======================= CSR build + gather aggregation ======================
__global__ void zero_small() {
    int i = blockIdx.x * blockDim.x + threadIdx.x;
    if (i < NN) g_cnt[i] = 0;
    if (i < DD) { g_colsum[i] = 0.f; g_colsumsq[i] = 0.f; }
}

__global__ __launch_bounds__(256) void hist_kernel(const int* __restrict__ ei, int E) {
    int e = blockIdx.x * blockDim.x + threadIdx.x;
    if (e < E) atomicAdd(&g_cnt[__ldg(&ei[E + e])], 1);
}

__global__ __launch_bounds__(1024) void scan_kernel() {
    __shared__ int tsum[1024];
    const int CH = (NN + 1023) / 1024;
    int t = threadIdx.x;
    int beg = t * CH, end = min(beg + CH, NN);
    int s = 0;
    for (int i = beg; i < end; ++i) s += g_cnt[i];
    tsum[t] = s;
    __syncthreads();
    for (int d = 1; d < 1024; d <<= 1) {
        int v = (t >= d) ? tsum[t - d] : 0;
        __syncthreads();
        tsum[t] += v;
        __syncthreads();
    }
    int excl = (t == 0) ? 0 : tsum[t - 1];
    for (int i = beg; i < end; ++i) {
        int c = g_cnt[i];
        g_off[i] = excl;
        g_woff[i] = excl;
        excl += c;
    }
    if (t == 1023) g_off[NN] = tsum[1023];
}

__global__ __launch_bounds__(256) void fill_kernel(const int* __restrict__ ei, int E) {
    int e = blockIdx.x * blockDim.x + threadIdx.x;
    if (e >= E) return;
    int src = __ldg(&ei[e]);
    int dst = __ldg(&ei[E + e]);
    int pos = atomicAdd(&g_woff[dst], 1);
    g_eidx[pos] = src;
}

// gather-reduce over fp16 x: one warp per node; fp32 accum; fp16 mean out.
// each lane owns 16 contiguous halfs (32 B = 2 uint4 loads per row), 4-edge MLP.
__global__ __launch_bounds__(256) void gather_kernel(int N) {
    int warp = (blockIdx.x * blockDim.x + threadIdx.x) >> 5;
    if (warp >= N) return;
    int lane = threadIdx.x & 31;
    int beg = g_off[warp], end = g_off[warp + 1];

    float acc[16];
#pragma unroll
    for (int i = 0; i < 16; ++i) acc[i] = 0.f;

    auto addrow = [&](uint4 p0, uint4 p1) {
        const __half2* h0 = (const __half2*)&p0;
        const __half2* h1 = (const __half2*)&p1;
#pragma unroll
        for (int j = 0; j < 4; ++j) {
            float2 a = __half22float2(h0[j]);
            acc[j * 2] += a.x; acc[j * 2 + 1] += a.y;
            float2 c = __half22float2(h1[j]);
            acc[8 + j * 2] += c.x; acc[8 + j * 2 + 1] += c.y;
        }
    };

    int e = beg;
    for (; e + 4 <= end; e += 4) {
        int s0 = __ldg(&g_eidx[e]);
        int s1 = __ldg(&g_eidx[e + 1]);
        int s2 = __ldg(&g_eidx[e + 2]);
        int s3 = __ldg(&g_eidx[e + 3]);
        const uint4* r0 = (const uint4*)&g_xhi[(size_t)s0 * DD + lane * 16];
        const uint4* r1 = (const uint4*)&g_xhi[(size_t)s1 * DD + lane * 16];
        const uint4* r2 = (const uint4*)&g_xhi[(size_t)s2 * DD + lane * 16];
        const uint4* r3 = (const uint4*)&g_xhi[(size_t)s3 * DD + lane * 16];
        uint4 a0 = r0[0], a1 = r0[1];
        uint4 b0 = r1[0], b1 = r1[1];
        uint4 c0 = r2[0], c1 = r2[1];
        uint4 d0 = r3[0], d1 = r3[1];
        addrow(a0, a1); addrow(b0, b1); addrow(c0, c1); addrow(d0, d1);
    }
    for (; e < end; ++e) {
        int s0 = __ldg(&g_eidx[e]);
        const uint4* r0 = (const uint4*)&g_xhi[(size_t)s0 * DD + lane * 16];
        uint4 a0 = r0[0], a1 = r0[1];
        addrow(a0, a1);
    }

    float inv = 1.0f / (float)max(end - beg, 1);
    uint4 o0, o1;
    __half2* ho0 = (__half2*)&o0;
    __half2* ho1 = (__half2*)&o1;
#pragma unroll
    for (int j = 0; j < 4; ++j) {
        ho0[j] = __floats2half2_rn(acc[j * 2] * inv, acc[j * 2 + 1] * inv);
        ho1[j] = __floats2half2_rn(acc[8 + j * 2] * inv, acc[8 + j * 2 + 1] * inv);
    }
    uint4* dst = (uint4*)&g_ag[(size_t)warp * DD + lane * 16];
    dst[0] = o0; dst[1] = o1;
}

// ======================= fp16 tensor GEMM (3-stage cp.async) =================
// h = mean_agg @ Wl^T + x @ Wr^T + bl ; fused per-column sum/sumsq
__global__ __launch_bounds__(256, 2) void gemm_mma(
    const float* __restrict__ bl, float* __restrict__ out, int N)
{
    extern __shared__ char sm[];
    const uint32_t s0 = smem_u32(sm);
    const int tid = threadIdx.x;
    const int lane = tid & 31, wid = tid >> 5;
    const int row0 = blockIdx.y * BM;
    const int col0 = blockIdx.x * BN;
    const int warp_m = (wid >> 1) * 32;
    const int warp_n = (wid & 1) * 64;

    float acc[2][8][4];
#pragma unroll
    for (int mf = 0; mf < 2; ++mf)
#pragma unroll
        for (int nf = 0; nf < 8; ++nf)
#pragma unroll
            for (int i = 0; i < 4; ++i) acc[mf][nf][i] = 0.f;

    auto issue_chunk = [&](int kt, int s) {
        const uint32_t sb = s0 + s * STAGE_B;
        const int kk = (kt & 15) * 32;
        const __half* Ah = (kt < 16) ? g_ag : g_xhi;
#pragma unroll
        for (int it = 0; it < 2; ++it) {
            int idx = it * 256 + tid;            // 0..511
            int r = idx >> 2, c16 = idx & 3;
            int rg = row0 + r;
            int nb = (rg < N) ? 16 : 0;
            int rc = min(rg, N - 1);
            const __half* sH = Ah + (size_t)rc * DD + kk + c16 * 8;
            uint32_t d = sb + (uint32_t)r * 80 + c16 * 16;
            CP16(d, sH, nb);
        }
#pragma unroll
        for (int it = 0; it < 2; ++it) {
            int idx = it * 256 + tid;
            int r = idx >> 2, c16 = idx & 3;
            const __half* sH = g_whi + (size_t)(col0 + r) * 1024 + kt * 32 + c16 * 8;
            uint32_t d = sb + 10240 + (uint32_t)r * 80 + c16 * 16;
            CP16(d, sH, 16);
        }
    };

    issue_chunk(0, 0); CP_COMMIT();
    issue_chunk(1, 1); CP_COMMIT();

    int s = 0;               // stage of chunk kt
    for (int kt = 0; kt < 32; ++kt) {
        if (kt == 31) { CP_WAIT0(); } else { CP_WAIT1(); }
        __syncthreads();     // chunk kt visible to all; stage (kt+2)%3 free

        if (kt + 2 < 32) {
            int s2 = s + 2; if (s2 >= 3) s2 -= 3;
            issue_chunk(kt + 2, s2);
            CP_COMMIT();
        }

        const uint32_t ahiB = s0 + s * STAGE_B;
        const uint32_t bhiB = ahiB + 10240;
#pragma unroll
        for (int ks = 0; ks < 2; ++ks) {
            const uint32_t k0b = ks * 32;
            uint32_t ah[2][4];
            {
                const int arow_l = (lane & 15);
                const uint32_t acol = k0b + ((lane >> 4) << 4);
#pragma unroll
                for (int mf = 0; mf < 2; ++mf) {
                    uint32_t off = (uint32_t)(warp_m + mf * 16 + arow_l) * 80 + acol;
                    LDSM4(ah[mf][0], ah[mf][1], ah[mf][2], ah[mf][3], ahiB + off);
                }
            }
            const int brow_l = (lane & 7) + ((lane >> 4) << 3);
            const uint32_t bcol = k0b + (((lane >> 3) & 1) << 4);
#pragma unroll
            for (int pair = 0; pair < 4; ++pair) {
                uint32_t boff = (uint32_t)(warp_n + pair * 16 + brow_l) * 80 + bcol;
                uint32_t bh[4];
                LDSM4(bh[0], bh[1], bh[2], bh[3], bhiB + boff);
#pragma unroll
                for (int mf = 0; mf < 2; ++mf)
#pragma unroll
                    for (int nfl = 0; nfl < 2; ++nfl) {
                        int nf = pair * 2 + nfl;
                        MMA_F16(acc[mf][nf], ah[mf], bh[nfl * 2], bh[nfl * 2 + 1]);
                    }
            }
        }
        if (++s >= 3) s = 0;
    }

    // ---- epilogue: +bias, store, fused column sum/sumsq --------------------
#pragma unroll
    for (int nf = 0; nf < 8; ++nf) {
        int c = col0 + warp_n + nf * 8 + 2 * (lane & 3);
        float2 bb = *(const float2*)&bl[c];
        float sA = 0.f, sB = 0.f, qA = 0.f, qB = 0.f;
#pragma unroll
        for (int mf = 0; mf < 2; ++mf) {
            int m = row0 + warp_m + mf * 16 + (lane >> 2);
            if (m < N) {
                float o0 = acc[mf][nf][0] + bb.x, o1 = acc[mf][nf][1] + bb.y;
                *(float2*)&out[(size_t)m * DD + c] = make_float2(o0, o1);
                sA += o0; sB += o1; qA += o0 * o0; qB += o1 * o1;
            }
            if (m + 8 < N) {
                float o0 = acc[mf][nf][2] + bb.x, o1 = acc[mf][nf][3] + bb.y;
                *(float2*)&out[(size_t)(m + 8) * DD + c] = make_float2(o0, o1);
                sA += o0; sB += o1; qA += o0 * o0; qB += o1 * o1;
            }
        }
#pragma unroll
        for (int d = 4; d < 32; d <<= 1) {
            sA += __shfl_xor_sync(0xffffffffu, sA, d);
            sB += __shfl_xor_sync(0xffffffffu, sB, d);
            qA += __shfl_xor_sync(0xffffffffu, qA, d);
            qB += __shfl_xor_sync(0xffffffffu, qB, d);
        }
        if (lane < 4) {
            atomicAdd(&g_colsum[c], sA);
            atomicAdd(&g_colsum[c + 1], sB);
            atomicAdd(&g_colsumsq[c], qA);
            atomicAdd(&g_colsumsq[c + 1], qB);
        }
    }
}

// ======================= BN stats + epilogue =================================
__global__ void stats_kernel(int N) {
    int c = threadIdx.x;
    float invn = 1.0f / (float)N;
    float mu = g_colsum[c] * invn;
    float var = g_colsumsq[c] * invn - mu * mu;
    g_mu[c] = mu;
    g_rstd[c] = rsqrtf(var + EPS);
}

__global__ __launch_bounds__(256) void final_kernel(
    const float* __restrict__ x, const float* __restrict__ gamma,
    const float* __restrict__ beta, float* __restrict__ out, int N)
{
    size_t idx = (size_t)blockIdx.x * blockDim.x + threadIdx.x;
    size_t total4 = (size_t)N * DD / 4;
    if (idx >= total4) return;
    int c = (int)((idx * 4) & (DD - 1));
    float4 h  = ((float4*)out)[idx];
    float4 xv = ((const float4*)x)[idx];
    float4 mu = *(const float4*)&g_mu[c];
    float4 rs = *(const float4*)&g_rstd[c];
    float4 ga = *(const float4*)&gamma[c];
    float4 be = *(const float4*)&beta[c];
    float4 o;
    o.x = fmaxf(fmaf((h.x - mu.x) * rs.x, ga.x, be.x), 0.f) + xv.x;
    o.y = fmaxf(fmaf((h.y - mu.y) * rs.y, ga.y, be.y), 0.f) + xv.y;
    o.z = fmaxf(fmaf((h.z - mu.z) * rs.z, ga.z, be.z), 0.f) + xv.z;
    o.w = fmaxf(fmaf((h.w - mu.w) * rs.w, ga.w, be.w), 0.f) + xv.w;
    ((float4*)out)[idx] = o;
}

// ---------------------------------------------------------------------------
extern "C" void kernel_launch(void* const* d_in, const int* in_sizes, int n_in,
                              void* d_out, int out_size)
{
    const float* x  = (const float*)d_in[0];
    const int*   ei = (const int*)d_in[1];
    const float* Wl = (const float*)d_in[2];
    const float* bl = (const float*)d_in[3];
    const float* Wr = (const float*)d_in[4];
    const float* ga = (const float*)d_in[5];
    const float* be = (const float*)d_in[6];
    float* out = (float*)d_out;

    int N = in_sizes[0] / DD;
    int E = in_sizes[1] / 2;

    zero_small<<<(NN + 255) / 256, 256>>>();
    hist_kernel<<<(E + 255) / 256, 256>>>(ei, E);
    scan_kernel<<<1, 1024>>>();
    fill_kernel<<<(E + 255) / 256, 256>>>(ei, E);

    size_t xtot4 = (size_t)N * DD / 4;
    conv_x<<<(int)((xtot4 + 255) / 256), 256>>>(x, N);
    conv_w<<<(512 * 1024 + 255) / 256, 256>>>(Wl, Wr);

    gather_kernel<<<(N + 7) / 8, 256>>>(N);

    static int smem_set = 0;
    if (!smem_set) {
        cudaFuncSetAttribute(gemm_mma, cudaFuncAttributeMaxDynamicSharedMemorySize,
                             SMEM_BYTES);
        smem_set = 1;
    }
    dim3 ggrid(DD / BN, (N + BM - 1) / BM);
    gemm_mma<<<ggrid, 256, SMEM_BYTES>>>(bl, out, N);

    stats_kernel<<<1, DD>>>(N);

    size_t tot4 = (size_t)N * DD / 4;
    final_kernel<<<(int)((tot4 + 255) / 256), 256>>>(x, ga, be, out, N);
}